// round 1
// baseline (speedup 1.0000x reference)
#include <cuda_runtime.h>
#include <cstdint>

#define M_NODES 100000
#define K_IN    256
#define N_OUT   128

// Scratch for support = x@W + b  (51.2 MB, static device array — no allocs)
__device__ float g_support[(size_t)M_NODES * N_OUT];

// ---------------------------------------------------------------------------
// Kernel 1: support = x @ W + b
// BM=128, BN=128(=full N), BK=16, 256 threads, 8x8 register tile per thread.
// ---------------------------------------------------------------------------
__global__ __launch_bounds__(256) void gemm_bias_kernel(
    const float* __restrict__ x,
    const float* __restrict__ W,
    const float* __restrict__ bias)
{
    __shared__ float As[16][128];   // A tile, k-major (transposed on load)
    __shared__ float Bs[16][128];   // W tile

    const int tid = threadIdx.x;
    const int tx  = tid & 15;       // 0..15 -> col group (8 cols each)
    const int ty  = tid >> 4;       // 0..15 -> row group (8 rows each)
    const int rowBase = blockIdx.x * 128;

    float acc[8][8];
    #pragma unroll
    for (int i = 0; i < 8; i++)
        #pragma unroll
        for (int j = 0; j < 8; j++) acc[i][j] = 0.f;

    for (int kb = 0; kb < K_IN; kb += 16) {
        // --- load x tile: 128 rows x 16 k -> 512 float4, 2 per thread ---
        #pragma unroll
        for (int i = 0; i < 2; i++) {
            int idx  = tid * 2 + i;          // 0..511
            int arow = idx >> 2;             // 0..127
            int ak   = (idx & 3) * 4;        // 0,4,8,12
            int grow = rowBase + arow;
            float4 v = make_float4(0.f, 0.f, 0.f, 0.f);
            if (grow < M_NODES)
                v = *(const float4*)(x + (size_t)grow * K_IN + kb + ak);
            As[ak + 0][arow] = v.x;
            As[ak + 1][arow] = v.y;
            As[ak + 2][arow] = v.z;
            As[ak + 3][arow] = v.w;
        }
        // --- load W tile: 16 k x 128 n -> 512 float4, 2 per thread ---
        #pragma unroll
        for (int i = 0; i < 2; i++) {
            int idx  = tid * 2 + i;          // 0..511
            int brow = idx >> 5;             // 0..15
            int bc   = (idx & 31) * 4;       // 0..124
            float4 v = *(const float4*)(W + (size_t)(kb + brow) * N_OUT + bc);
            *(float4*)&Bs[brow][bc] = v;
        }
        __syncthreads();

        #pragma unroll
        for (int k = 0; k < 16; k++) {
            float a[8], bfrag[8];
            #pragma unroll
            for (int i = 0; i < 8; i++) a[i] = As[k][ty * 8 + i];
            #pragma unroll
            for (int j = 0; j < 8; j++) bfrag[j] = Bs[k][tx * 8 + j];
            #pragma unroll
            for (int i = 0; i < 8; i++)
                #pragma unroll
                for (int j = 0; j < 8; j++)
                    acc[i][j] += a[i] * bfrag[j];
        }
        __syncthreads();
    }

    // --- store with bias ---
    #pragma unroll
    for (int i = 0; i < 8; i++) {
        int grow = rowBase + ty * 8 + i;
        if (grow < M_NODES) {
            #pragma unroll
            for (int j = 0; j < 8; j += 4) {
                int gcol = tx * 8 + j;
                float4 o;
                o.x = acc[i][j + 0] + bias[gcol + 0];
                o.y = acc[i][j + 1] + bias[gcol + 1];
                o.z = acc[i][j + 2] + bias[gcol + 2];
                o.w = acc[i][j + 3] + bias[gcol + 3];
                *(float4*)(g_support + (size_t)grow * N_OUT + gcol) = o;
            }
        }
    }
}

// ---------------------------------------------------------------------------
// Kernel 2: zero the output (d_out is poisoned by the harness)
// ---------------------------------------------------------------------------
__global__ void zero_kernel(float4* __restrict__ out, int n4)
{
    int i = blockIdx.x * blockDim.x + threadIdx.x;
    if (i < n4) out[i] = make_float4(0.f, 0.f, 0.f, 0.f);
}

// ---------------------------------------------------------------------------
// Kernel 3: edge scatter. One warp per edge; each lane handles one float4
// (4 features) and issues a single vector RED (red.global.add.v4.f32).
// support and out both fit in L2 (51.2 MB each), so gathers are L2 hits and
// the reduction stays in the LTS atomic units.
// ---------------------------------------------------------------------------
__global__ __launch_bounds__(256) void scatter_kernel(
    const int*   __restrict__ erow,
    const int*   __restrict__ ecol,
    const float* __restrict__ eval,
    float*       __restrict__ out,
    int E)
{
    int gw   = (blockIdx.x * blockDim.x + threadIdx.x) >> 5;   // global warp = edge
    int lane = threadIdx.x & 31;
    if (gw >= E) return;

    int   r = erow[gw];
    int   c = ecol[gw];
    float v = eval[gw];

    const float4* src = (const float4*)(g_support + (size_t)c * N_OUT);
    float4 m = src[lane];
    m.x *= v; m.y *= v; m.z *= v; m.w *= v;

    float4* dst = (float4*)(out + (size_t)r * N_OUT) + lane;
    asm volatile("red.global.add.v4.f32 [%0], {%1, %2, %3, %4};"
                 :: "l"(dst), "f"(m.x), "f"(m.y), "f"(m.z), "f"(m.w)
                 : "memory");
}

// ---------------------------------------------------------------------------
// Kernel 4: ReLU in place
// ---------------------------------------------------------------------------
__global__ void relu_kernel(float4* __restrict__ out, int n4)
{
    int i = blockIdx.x * blockDim.x + threadIdx.x;
    if (i < n4) {
        float4 v = out[i];
        v.x = fmaxf(v.x, 0.f);
        v.y = fmaxf(v.y, 0.f);
        v.z = fmaxf(v.z, 0.f);
        v.w = fmaxf(v.w, 0.f);
        out[i] = v;
    }
}

// ---------------------------------------------------------------------------
extern "C" void kernel_launch(void* const* d_in, const int* in_sizes, int n_in,
                              void* d_out, int out_size)
{
    const float* x    = (const float*)d_in[0];
    const int*   erow = (const int*)  d_in[1];
    const int*   ecol = (const int*)  d_in[2];
    const float* eval = (const float*)d_in[3];
    const float* W    = (const float*)d_in[4];
    const float* bias = (const float*)d_in[5];
    float* out = (float*)d_out;

    const int E  = in_sizes[1];
    const int n4 = out_size / 4;            // 12.8M floats -> 3.2M float4

    // 1) support = x @ W + b
    int gemmBlocks = (M_NODES + 127) / 128;  // 782
    gemm_bias_kernel<<<gemmBlocks, 256>>>(x, W, bias);

    // 2) out = 0
    zero_kernel<<<(n4 + 255) / 256, 256>>>((float4*)out, n4);

    // 3) out[r] += val * support[c]   (one warp per edge, v4 RED)
    int warpsPerBlock = 256 / 32;            // 8
    int scatterBlocks = (E + warpsPerBlock - 1) / warpsPerBlock;
    scatter_kernel<<<scatterBlocks, 256>>>(erow, ecol, eval, out, E);

    // 4) ReLU
    relu_kernel<<<(n4 + 255) / 256, 256>>>((float4*)out, n4);
}

// round 2
// speedup vs baseline: 1.4061x; 1.4061x over previous
#include <cuda_runtime.h>
#include <cstdint>

#define M_NODES 100000
#define K_IN    256
#define N_OUT   128

// Scratch for support = x@W + b  (51.2 MB, static device array — no allocs)
__device__ float g_support[(size_t)M_NODES * N_OUT];

__device__ __forceinline__ uint32_t f2tf(float f)
{
    uint32_t u;
    asm("cvt.rna.tf32.f32 %0, %1;" : "=r"(u) : "f"(f));
    return u;
}

// ---------------------------------------------------------------------------
// Kernel 1: support = x @ W + b   via TF32 mma.sync.m16n8k8
// CTA: 128(M) x 128(N=full), BK=32, 256 threads = 8 warps (4 Mwarps x 2 Nwarps)
// Warp tile: 32(M) x 64(N) = 2 mtiles x 8 ntiles of m16n8k8.
// Smem strides chosen so fragment LDS addresses are bank-bijective:
//   As stride 36:  bank = (4g + tg) % 32  -> conflict-free
//   Bs stride 136: bank = (8tg + g) % 32  -> conflict-free
// ---------------------------------------------------------------------------
__global__ __launch_bounds__(256) void gemm_tf32_kernel(
    const float* __restrict__ x,
    const float* __restrict__ W,
    const float* __restrict__ bias)
{
    __shared__ uint32_t As[128][36];
    __shared__ uint32_t Bs[32][136];

    const int tid   = threadIdx.x;
    const int lane  = tid & 31;
    const int wid   = tid >> 5;
    const int warpM = wid & 3;     // 0..3  -> 32-row slice
    const int warpN = wid >> 2;    // 0..1  -> 64-col slice
    const int g     = lane >> 2;   // groupID 0..7
    const int tg    = lane & 3;    // threadID in group 0..3
    const int rowBase = blockIdx.x * 128;

    float acc[2][8][4];
    #pragma unroll
    for (int mt = 0; mt < 2; mt++)
        #pragma unroll
        for (int nt = 0; nt < 8; nt++)
            #pragma unroll
            for (int r = 0; r < 4; r++) acc[mt][nt][r] = 0.f;

    for (int kb = 0; kb < K_IN; kb += 32) {
        // ---- load x tile: 128 rows x 32 k = 1024 float4, 4 per thread ----
        #pragma unroll
        for (int i = 0; i < 4; i++) {
            int idx  = tid + i * 256;        // 0..1023
            int row  = idx >> 3;             // 0..127
            int k4   = (idx & 7) * 4;        // 0,4,...,28
            int grow = rowBase + row;
            float4 v = make_float4(0.f, 0.f, 0.f, 0.f);
            if (grow < M_NODES)
                v = *(const float4*)(x + (size_t)grow * K_IN + kb + k4);
            As[row][k4 + 0] = f2tf(v.x);
            As[row][k4 + 1] = f2tf(v.y);
            As[row][k4 + 2] = f2tf(v.z);
            As[row][k4 + 3] = f2tf(v.w);
        }
        // ---- load W tile: 32 k x 128 n = 1024 float4, 4 per thread ----
        #pragma unroll
        for (int i = 0; i < 4; i++) {
            int idx  = tid + i * 256;
            int krow = idx >> 5;             // 0..31
            int n4   = (idx & 31) * 4;       // 0..124
            float4 v = *(const float4*)(W + (size_t)(kb + krow) * N_OUT + n4);
            Bs[krow][n4 + 0] = f2tf(v.x);
            Bs[krow][n4 + 1] = f2tf(v.y);
            Bs[krow][n4 + 2] = f2tf(v.z);
            Bs[krow][n4 + 3] = f2tf(v.w);
        }
        __syncthreads();

        #pragma unroll
        for (int ks = 0; ks < 4; ks++) {
            const int kk = ks * 8;
            uint32_t bfr[8][2];
            #pragma unroll
            for (int nt = 0; nt < 8; nt++) {
                int col = warpN * 64 + nt * 8 + g;
                bfr[nt][0] = Bs[kk + tg][col];
                bfr[nt][1] = Bs[kk + tg + 4][col];
            }
            #pragma unroll
            for (int mt = 0; mt < 2; mt++) {
                int r0 = warpM * 32 + mt * 16 + g;
                uint32_t a0 = As[r0][kk + tg];
                uint32_t a1 = As[r0 + 8][kk + tg];
                uint32_t a2 = As[r0][kk + tg + 4];
                uint32_t a3 = As[r0 + 8][kk + tg + 4];
                #pragma unroll
                for (int nt = 0; nt < 8; nt++) {
                    asm volatile(
                        "mma.sync.aligned.m16n8k8.row.col.f32.tf32.tf32.f32 "
                        "{%0,%1,%2,%3}, {%4,%5,%6,%7}, {%8,%9}, {%0,%1,%2,%3};"
                        : "+f"(acc[mt][nt][0]), "+f"(acc[mt][nt][1]),
                          "+f"(acc[mt][nt][2]), "+f"(acc[mt][nt][3])
                        : "r"(a0), "r"(a1), "r"(a2), "r"(a3),
                          "r"(bfr[nt][0]), "r"(bfr[nt][1]));
                }
            }
        }
        __syncthreads();
    }

    // ---- epilogue: += bias, store to g_support ----
    #pragma unroll
    for (int nt = 0; nt < 8; nt++) {
        int col = warpN * 64 + nt * 8 + tg * 2;
        float2 bv = *(const float2*)(bias + col);
        #pragma unroll
        for (int mt = 0; mt < 2; mt++) {
            int row0 = rowBase + warpM * 32 + mt * 16 + g;
            if (row0 < M_NODES) {
                float2 o;
                o.x = acc[mt][nt][0] + bv.x;
                o.y = acc[mt][nt][1] + bv.y;
                *(float2*)(g_support + (size_t)row0 * N_OUT + col) = o;
            }
            int row1 = row0 + 8;
            if (row1 < M_NODES) {
                float2 o;
                o.x = acc[mt][nt][2] + bv.x;
                o.y = acc[mt][nt][3] + bv.y;
                *(float2*)(g_support + (size_t)row1 * N_OUT + col) = o;
            }
        }
    }
}

// ---------------------------------------------------------------------------
// Kernel 2: zero the output (d_out is poisoned by the harness)
// ---------------------------------------------------------------------------
__global__ void zero_kernel(float4* __restrict__ out, int n4)
{
    int i = blockIdx.x * blockDim.x + threadIdx.x;
    if (i < n4) out[i] = make_float4(0.f, 0.f, 0.f, 0.f);
}

// ---------------------------------------------------------------------------
// Kernel 3: edge scatter. One warp per edge; each lane handles one float4
// (4 features) and issues a single vector RED (red.global.add.v4.f32).
// ---------------------------------------------------------------------------
__global__ __launch_bounds__(256) void scatter_kernel(
    const int*   __restrict__ erow,
    const int*   __restrict__ ecol,
    const float* __restrict__ eval,
    float*       __restrict__ out,
    int E)
{
    int gw   = (blockIdx.x * blockDim.x + threadIdx.x) >> 5;   // global warp = edge
    int lane = threadIdx.x & 31;
    if (gw >= E) return;

    int   r = erow[gw];
    int   c = ecol[gw];
    float v = eval[gw];

    const float4* src = (const float4*)(g_support + (size_t)c * N_OUT);
    float4 m = src[lane];
    m.x *= v; m.y *= v; m.z *= v; m.w *= v;

    float4* dst = (float4*)(out + (size_t)r * N_OUT) + lane;
    asm volatile("red.global.add.v4.f32 [%0], {%1, %2, %3, %4};"
                 :: "l"(dst), "f"(m.x), "f"(m.y), "f"(m.z), "f"(m.w)
                 : "memory");
}

// ---------------------------------------------------------------------------
// Kernel 4: ReLU in place
// ---------------------------------------------------------------------------
__global__ void relu_kernel(float4* __restrict__ out, int n4)
{
    int i = blockIdx.x * blockDim.x + threadIdx.x;
    if (i < n4) {
        float4 v = out[i];
        v.x = fmaxf(v.x, 0.f);
        v.y = fmaxf(v.y, 0.f);
        v.z = fmaxf(v.z, 0.f);
        v.w = fmaxf(v.w, 0.f);
        out[i] = v;
    }
}

// ---------------------------------------------------------------------------
extern "C" void kernel_launch(void* const* d_in, const int* in_sizes, int n_in,
                              void* d_out, int out_size)
{
    const float* x    = (const float*)d_in[0];
    const int*   erow = (const int*)  d_in[1];
    const int*   ecol = (const int*)  d_in[2];
    const float* eval = (const float*)d_in[3];
    const float* W    = (const float*)d_in[4];
    const float* bias = (const float*)d_in[5];
    float* out = (float*)d_out;

    const int E  = in_sizes[1];
    const int n4 = out_size / 4;

    // 1) support = x @ W + b  (TF32 tensor cores)
    int gemmBlocks = (M_NODES + 127) / 128;  // 782
    gemm_tf32_kernel<<<gemmBlocks, 256>>>(x, W, bias);

    // 2) out = 0
    zero_kernel<<<(n4 + 255) / 256, 256>>>((float4*)out, n4);

    // 3) out[r] += val * support[c]   (one warp per edge, v4 RED)
    int warpsPerBlock = 256 / 32;
    int scatterBlocks = (E + warpsPerBlock - 1) / warpsPerBlock;
    scatter_kernel<<<scatterBlocks, 256>>>(erow, ecol, eval, out, E);

    // 4) ReLU
    relu_kernel<<<(n4 + 255) / 256, 256>>>((float4*)out, n4);
}

// round 3
// speedup vs baseline: 2.2778x; 1.6199x over previous
#include <cuda_runtime.h>
#include <cstdint>

#define M_NODES 100000
#define K_IN    256
#define N_OUT   128
#define MAX_E   1600000
#define SCAN_BS 1024

// ---- static device scratch (no allocs allowed) ----
__device__ float g_support[(size_t)M_NODES * N_OUT];   // 51.2 MB
__device__ int   g_cnt[M_NODES];
__device__ int   g_start[M_NODES + 1];
__device__ int   g_cursor[M_NODES];
__device__ int   g_bsums[128];
__device__ uint2 g_edges[MAX_E];                       // packed (col, val_bits)

__device__ __forceinline__ uint32_t f2tf(float f)
{
    uint32_t u;
    asm("cvt.rna.tf32.f32 %0, %1;" : "=r"(u) : "f"(f));
    return u;
}

// ---------------------------------------------------------------------------
// Kernel 1: support = x @ W + b   via TF32 mma.sync.m16n8k8 (unchanged)
// ---------------------------------------------------------------------------
__global__ __launch_bounds__(256) void gemm_tf32_kernel(
    const float* __restrict__ x,
    const float* __restrict__ W,
    const float* __restrict__ bias)
{
    __shared__ uint32_t As[128][36];
    __shared__ uint32_t Bs[32][136];

    const int tid   = threadIdx.x;
    const int lane  = tid & 31;
    const int wid   = tid >> 5;
    const int warpM = wid & 3;
    const int warpN = wid >> 2;
    const int g     = lane >> 2;
    const int tg    = lane & 3;
    const int rowBase = blockIdx.x * 128;

    float acc[2][8][4];
    #pragma unroll
    for (int mt = 0; mt < 2; mt++)
        #pragma unroll
        for (int nt = 0; nt < 8; nt++)
            #pragma unroll
            for (int r = 0; r < 4; r++) acc[mt][nt][r] = 0.f;

    for (int kb = 0; kb < K_IN; kb += 32) {
        #pragma unroll
        for (int i = 0; i < 4; i++) {
            int idx  = tid + i * 256;
            int row  = idx >> 3;
            int k4   = (idx & 7) * 4;
            int grow = rowBase + row;
            float4 v = make_float4(0.f, 0.f, 0.f, 0.f);
            if (grow < M_NODES)
                v = *(const float4*)(x + (size_t)grow * K_IN + kb + k4);
            As[row][k4 + 0] = f2tf(v.x);
            As[row][k4 + 1] = f2tf(v.y);
            As[row][k4 + 2] = f2tf(v.z);
            As[row][k4 + 3] = f2tf(v.w);
        }
        #pragma unroll
        for (int i = 0; i < 4; i++) {
            int idx  = tid + i * 256;
            int krow = idx >> 5;
            int n4   = (idx & 31) * 4;
            float4 v = *(const float4*)(W + (size_t)(kb + krow) * N_OUT + n4);
            Bs[krow][n4 + 0] = f2tf(v.x);
            Bs[krow][n4 + 1] = f2tf(v.y);
            Bs[krow][n4 + 2] = f2tf(v.z);
            Bs[krow][n4 + 3] = f2tf(v.w);
        }
        __syncthreads();

        #pragma unroll
        for (int ks = 0; ks < 4; ks++) {
            const int kk = ks * 8;
            uint32_t bfr[8][2];
            #pragma unroll
            for (int nt = 0; nt < 8; nt++) {
                int col = warpN * 64 + nt * 8 + g;
                bfr[nt][0] = Bs[kk + tg][col];
                bfr[nt][1] = Bs[kk + tg + 4][col];
            }
            #pragma unroll
            for (int mt = 0; mt < 2; mt++) {
                int r0 = warpM * 32 + mt * 16 + g;
                uint32_t a0 = As[r0][kk + tg];
                uint32_t a1 = As[r0 + 8][kk + tg];
                uint32_t a2 = As[r0][kk + tg + 4];
                uint32_t a3 = As[r0 + 8][kk + tg + 4];
                #pragma unroll
                for (int nt = 0; nt < 8; nt++) {
                    asm volatile(
                        "mma.sync.aligned.m16n8k8.row.col.f32.tf32.tf32.f32 "
                        "{%0,%1,%2,%3}, {%4,%5,%6,%7}, {%8,%9}, {%0,%1,%2,%3};"
                        : "+f"(acc[mt][nt][0]), "+f"(acc[mt][nt][1]),
                          "+f"(acc[mt][nt][2]), "+f"(acc[mt][nt][3])
                        : "r"(a0), "r"(a1), "r"(a2), "r"(a3),
                          "r"(bfr[nt][0]), "r"(bfr[nt][1]));
                }
            }
        }
        __syncthreads();
    }

    #pragma unroll
    for (int nt = 0; nt < 8; nt++) {
        int col = warpN * 64 + nt * 8 + tg * 2;
        float2 bv = *(const float2*)(bias + col);
        #pragma unroll
        for (int mt = 0; mt < 2; mt++) {
            int row0 = rowBase + warpM * 32 + mt * 16 + g;
            if (row0 < M_NODES) {
                float2 o;
                o.x = acc[mt][nt][0] + bv.x;
                o.y = acc[mt][nt][1] + bv.y;
                *(float2*)(g_support + (size_t)row0 * N_OUT + col) = o;
            }
            int row1 = row0 + 8;
            if (row1 < M_NODES) {
                float2 o;
                o.x = acc[mt][nt][2] + bv.x;
                o.y = acc[mt][nt][3] + bv.y;
                *(float2*)(g_support + (size_t)row1 * N_OUT + col) = o;
            }
        }
    }
}

// ---------------------------------------------------------------------------
// CSR build: histogram -> scan -> permute
// ---------------------------------------------------------------------------
__global__ void zero_cnt_kernel(int n)
{
    int i = blockIdx.x * blockDim.x + threadIdx.x;
    if (i < n) g_cnt[i] = 0;
}

__global__ void hist_kernel(const int* __restrict__ erow, int E)
{
    int i = blockIdx.x * blockDim.x + threadIdx.x;
    if (i < E) atomicAdd(&g_cnt[erow[i]], 1);
}

// Block-wise exclusive scan (1024/block), writes block totals
__global__ __launch_bounds__(SCAN_BS) void scan_blocks_kernel(int n)
{
    __shared__ int sm[SCAN_BS];
    int i = blockIdx.x * SCAN_BS + threadIdx.x;
    int v = (i < n) ? g_cnt[i] : 0;
    sm[threadIdx.x] = v;
    __syncthreads();
    #pragma unroll
    for (int off = 1; off < SCAN_BS; off <<= 1) {
        int t = (threadIdx.x >= off) ? sm[threadIdx.x - off] : 0;
        __syncthreads();
        sm[threadIdx.x] += t;
        __syncthreads();
    }
    if (i < n) g_start[i] = sm[threadIdx.x] - v;    // exclusive
    if (threadIdx.x == SCAN_BS - 1) g_bsums[blockIdx.x] = sm[SCAN_BS - 1];
}

// Single-block exclusive scan of block sums (nb <= 128)
__global__ __launch_bounds__(128) void scan_small_kernel(int nb)
{
    __shared__ int sm[128];
    int v = (threadIdx.x < nb) ? g_bsums[threadIdx.x] : 0;
    sm[threadIdx.x] = v;
    __syncthreads();
    #pragma unroll
    for (int off = 1; off < 128; off <<= 1) {
        int t = (threadIdx.x >= off) ? sm[threadIdx.x - off] : 0;
        __syncthreads();
        sm[threadIdx.x] += t;
        __syncthreads();
    }
    if (threadIdx.x < nb) g_bsums[threadIdx.x] = sm[threadIdx.x] - v;
}

__global__ void scan_add_kernel(int n, int E)
{
    int i = blockIdx.x * blockDim.x + threadIdx.x;
    if (i < n) {
        int s = g_start[i] + g_bsums[i >> 10];
        g_start[i]  = s;
        g_cursor[i] = s;
    }
    if (i == 0) g_start[n] = E;
}

__global__ void permute_kernel(const int* __restrict__ erow,
                               const int* __restrict__ ecol,
                               const float* __restrict__ eval, int E)
{
    int i = blockIdx.x * blockDim.x + threadIdx.x;
    if (i < E) {
        int r   = erow[i];
        int pos = atomicAdd(&g_cursor[r], 1);
        g_edges[pos] = make_uint2((unsigned)ecol[i], __float_as_uint(eval[i]));
    }
}

// ---------------------------------------------------------------------------
// Gather: one warp per output row, lane owns 4 features (float4).
// out[r] = relu( sum_e val_e * support[col_e] ). Atomic-free, fused ReLU.
// ---------------------------------------------------------------------------
__global__ __launch_bounds__(256) void gather_kernel(float* __restrict__ out)
{
    int row  = (blockIdx.x * blockDim.x + threadIdx.x) >> 5;
    int lane = threadIdx.x & 31;
    if (row >= M_NODES) return;

    int s = g_start[row];
    int e = g_start[row + 1];

    float4 acc0 = make_float4(0.f, 0.f, 0.f, 0.f);
    float4 acc1 = make_float4(0.f, 0.f, 0.f, 0.f);

    for (int base = s; base < e; base += 32) {
        int m = min(32, e - base);
        uint2 ed = (base + lane < e) ? g_edges[base + lane] : make_uint2(0u, 0u);

        int j = 0;
        for (; j + 2 <= m; j += 2) {
            unsigned c0 = __shfl_sync(0xffffffffu, ed.x, j);
            float    v0 = __uint_as_float(__shfl_sync(0xffffffffu, ed.y, j));
            unsigned c1 = __shfl_sync(0xffffffffu, ed.x, j + 1);
            float    v1 = __uint_as_float(__shfl_sync(0xffffffffu, ed.y, j + 1));
            float4 s0 = *((const float4*)(g_support + (size_t)c0 * N_OUT) + lane);
            float4 s1 = *((const float4*)(g_support + (size_t)c1 * N_OUT) + lane);
            acc0.x += v0 * s0.x; acc0.y += v0 * s0.y;
            acc0.z += v0 * s0.z; acc0.w += v0 * s0.w;
            acc1.x += v1 * s1.x; acc1.y += v1 * s1.y;
            acc1.z += v1 * s1.z; acc1.w += v1 * s1.w;
        }
        if (j < m) {
            unsigned c0 = __shfl_sync(0xffffffffu, ed.x, j);
            float    v0 = __uint_as_float(__shfl_sync(0xffffffffu, ed.y, j));
            float4 s0 = *((const float4*)(g_support + (size_t)c0 * N_OUT) + lane);
            acc0.x += v0 * s0.x; acc0.y += v0 * s0.y;
            acc0.z += v0 * s0.z; acc0.w += v0 * s0.w;
        }
    }

    float4 o;
    o.x = fmaxf(acc0.x + acc1.x, 0.f);
    o.y = fmaxf(acc0.y + acc1.y, 0.f);
    o.z = fmaxf(acc0.z + acc1.z, 0.f);
    o.w = fmaxf(acc0.w + acc1.w, 0.f);
    __stcs((float4*)(out + (size_t)row * N_OUT) + lane, o);
}

// ---------------------------------------------------------------------------
extern "C" void kernel_launch(void* const* d_in, const int* in_sizes, int n_in,
                              void* d_out, int out_size)
{
    const float* x    = (const float*)d_in[0];
    const int*   erow = (const int*)  d_in[1];
    const int*   ecol = (const int*)  d_in[2];
    const float* eval = (const float*)d_in[3];
    const float* W    = (const float*)d_in[4];
    const float* bias = (const float*)d_in[5];
    float* out = (float*)d_out;

    const int E = in_sizes[1];

    // 1) support = x @ W + b  (TF32 tensor cores)
    gemm_tf32_kernel<<<(M_NODES + 127) / 128, 256>>>(x, W, bias);

    // 2) CSR build
    zero_cnt_kernel<<<(M_NODES + 255) / 256, 256>>>(M_NODES);
    hist_kernel<<<(E + 255) / 256, 256>>>(erow, E);
    int nb = (M_NODES + SCAN_BS - 1) / SCAN_BS;           // 98
    scan_blocks_kernel<<<nb, SCAN_BS>>>(M_NODES);
    scan_small_kernel<<<1, 128>>>(nb);
    scan_add_kernel<<<(M_NODES + 255) / 256, 256>>>(M_NODES, E);
    permute_kernel<<<(E + 255) / 256, 256>>>(erow, ecol, eval, E);

    // 3) fused gather + ReLU (atomic-free)
    gather_kernel<<<(M_NODES * 32 + 255) / 256, 256>>>(out);
}

// round 4
// speedup vs baseline: 2.3886x; 1.0487x over previous
#include <cuda_runtime.h>
#include <cuda_fp16.h>
#include <cstdint>

#define M_NODES 100000
#define K_IN    256
#define N_OUT   128
#define MAX_E   1600000
#define SCAN_BS 1024

// ---- static device scratch (no allocs allowed) ----
__device__ __half g_support_h[(size_t)M_NODES * N_OUT];   // 25.6 MB, fp16
__device__ int    g_cnt[M_NODES];
__device__ int    g_start[M_NODES + 1];
__device__ int    g_cursor[M_NODES];
__device__ int    g_bsums[128];
__device__ uint2  g_edges[MAX_E];                         // packed (col, val_bits)

__device__ __forceinline__ uint32_t f2tf(float f)
{
    uint32_t u;
    asm("cvt.rna.tf32.f32 %0, %1;" : "=r"(u) : "f"(f));
    return u;
}

// ---------------------------------------------------------------------------
// Kernel 1: support = x @ W + b   via TF32 mma.sync.m16n8k8
// Double-buffered smem (dynamic, 2 stages) with register prefetch of the
// next k-tile's global loads, issued before compute to hide LDG latency.
// Output stored as fp16 (half2 packed).
// Smem strides keep fragment LDS bank-bijective (As stride 36, Bs stride 136).
// ---------------------------------------------------------------------------
__global__ __launch_bounds__(256) void gemm_tf32_kernel(
    const float* __restrict__ x,
    const float* __restrict__ W,
    const float* __restrict__ bias)
{
    extern __shared__ uint32_t smbuf[];
    uint32_t* AsBase = smbuf;                    // [2][128][36]
    uint32_t* BsBase = smbuf + 2 * 128 * 36;     // [2][32][136]

    const int tid   = threadIdx.x;
    const int lane  = tid & 31;
    const int wid   = tid >> 5;
    const int warpM = wid & 3;
    const int warpN = wid >> 2;
    const int g     = lane >> 2;
    const int tg    = lane & 3;
    const int rowBase = blockIdx.x * 128;

    float acc[2][8][4];
    #pragma unroll
    for (int mt = 0; mt < 2; mt++)
        #pragma unroll
        for (int nt = 0; nt < 8; nt++)
            #pragma unroll
            for (int r = 0; r < 4; r++) acc[mt][nt][r] = 0.f;

    float4 ar[4], br[4];

    auto loadTiles = [&](int kb) {
        #pragma unroll
        for (int i = 0; i < 4; i++) {
            int idx  = tid + i * 256;
            int row  = idx >> 3;
            int k4   = (idx & 7) * 4;
            int grow = rowBase + row;
            ar[i] = (grow < M_NODES)
                  ? *(const float4*)(x + (size_t)grow * K_IN + kb + k4)
                  : make_float4(0.f, 0.f, 0.f, 0.f);
        }
        #pragma unroll
        for (int i = 0; i < 4; i++) {
            int idx  = tid + i * 256;
            int krow = idx >> 5;
            int n4   = (idx & 31) * 4;
            br[i] = *(const float4*)(W + (size_t)(kb + krow) * N_OUT + n4);
        }
    };

    auto storeTiles = [&](int s) {
        uint32_t* A = AsBase + s * 128 * 36;
        uint32_t* B = BsBase + s * 32 * 136;
        #pragma unroll
        for (int i = 0; i < 4; i++) {
            int idx = tid + i * 256;
            int row = idx >> 3;
            int k4  = (idx & 7) * 4;
            A[row * 36 + k4 + 0] = f2tf(ar[i].x);
            A[row * 36 + k4 + 1] = f2tf(ar[i].y);
            A[row * 36 + k4 + 2] = f2tf(ar[i].z);
            A[row * 36 + k4 + 3] = f2tf(ar[i].w);
        }
        #pragma unroll
        for (int i = 0; i < 4; i++) {
            int idx  = tid + i * 256;
            int krow = idx >> 5;
            int n4   = (idx & 31) * 4;
            B[krow * 136 + n4 + 0] = f2tf(br[i].x);
            B[krow * 136 + n4 + 1] = f2tf(br[i].y);
            B[krow * 136 + n4 + 2] = f2tf(br[i].z);
            B[krow * 136 + n4 + 3] = f2tf(br[i].w);
        }
    };

    auto compute = [&](int s) {
        const uint32_t* A = AsBase + s * 128 * 36;
        const uint32_t* B = BsBase + s * 32 * 136;
        #pragma unroll
        for (int ks = 0; ks < 4; ks++) {
            const int kk = ks * 8;
            uint32_t bfr[8][2];
            #pragma unroll
            for (int nt = 0; nt < 8; nt++) {
                int col = warpN * 64 + nt * 8 + g;
                bfr[nt][0] = B[(kk + tg) * 136 + col];
                bfr[nt][1] = B[(kk + tg + 4) * 136 + col];
            }
            #pragma unroll
            for (int mt = 0; mt < 2; mt++) {
                int r0 = warpM * 32 + mt * 16 + g;
                uint32_t a0 = A[r0 * 36 + kk + tg];
                uint32_t a1 = A[(r0 + 8) * 36 + kk + tg];
                uint32_t a2 = A[r0 * 36 + kk + tg + 4];
                uint32_t a3 = A[(r0 + 8) * 36 + kk + tg + 4];
                #pragma unroll
                for (int nt = 0; nt < 8; nt++) {
                    asm volatile(
                        "mma.sync.aligned.m16n8k8.row.col.f32.tf32.tf32.f32 "
                        "{%0,%1,%2,%3}, {%4,%5,%6,%7}, {%8,%9}, {%0,%1,%2,%3};"
                        : "+f"(acc[mt][nt][0]), "+f"(acc[mt][nt][1]),
                          "+f"(acc[mt][nt][2]), "+f"(acc[mt][nt][3])
                        : "r"(a0), "r"(a1), "r"(a2), "r"(a3),
                          "r"(bfr[nt][0]), "r"(bfr[nt][1]));
                }
            }
        }
    };

    loadTiles(0);
    storeTiles(0);
    __syncthreads();

    #pragma unroll
    for (int kb = 0; kb < 8; kb++) {
        int cur = kb & 1;
        if (kb < 7) loadTiles((kb + 1) * 32);   // prefetch next tile (LDG in flight)
        compute(cur);
        if (kb < 7) {
            storeTiles(cur ^ 1);
            __syncthreads();
        }
    }

    // ---- epilogue: += bias, pack fp16, store ----
    #pragma unroll
    for (int nt = 0; nt < 8; nt++) {
        int col = warpN * 64 + nt * 8 + tg * 2;
        float2 bv = *(const float2*)(bias + col);
        #pragma unroll
        for (int mt = 0; mt < 2; mt++) {
            int row0 = rowBase + warpM * 32 + mt * 16 + g;
            if (row0 < M_NODES) {
                __half2 h = __floats2half2_rn(acc[mt][nt][0] + bv.x,
                                              acc[mt][nt][1] + bv.y);
                *(__half2*)(g_support_h + (size_t)row0 * N_OUT + col) = h;
            }
            int row1 = row0 + 8;
            if (row1 < M_NODES) {
                __half2 h = __floats2half2_rn(acc[mt][nt][2] + bv.x,
                                              acc[mt][nt][3] + bv.y);
                *(__half2*)(g_support_h + (size_t)row1 * N_OUT + col) = h;
            }
        }
    }
}

// ---------------------------------------------------------------------------
// CSR build: histogram -> scan -> permute
// ---------------------------------------------------------------------------
__global__ void zero_cnt_kernel(int n)
{
    int i = blockIdx.x * blockDim.x + threadIdx.x;
    if (i < n) g_cnt[i] = 0;
}

__global__ void hist_kernel(const int* __restrict__ erow, int E)
{
    int i = blockIdx.x * blockDim.x + threadIdx.x;
    if (i < E) atomicAdd(&g_cnt[erow[i]], 1);
}

__global__ __launch_bounds__(SCAN_BS) void scan_blocks_kernel(int n)
{
    __shared__ int sm[SCAN_BS];
    int i = blockIdx.x * SCAN_BS + threadIdx.x;
    int v = (i < n) ? g_cnt[i] : 0;
    sm[threadIdx.x] = v;
    __syncthreads();
    #pragma unroll
    for (int off = 1; off < SCAN_BS; off <<= 1) {
        int t = (threadIdx.x >= off) ? sm[threadIdx.x - off] : 0;
        __syncthreads();
        sm[threadIdx.x] += t;
        __syncthreads();
    }
    if (i < n) g_start[i] = sm[threadIdx.x] - v;
    if (threadIdx.x == SCAN_BS - 1) g_bsums[blockIdx.x] = sm[SCAN_BS - 1];
}

__global__ __launch_bounds__(128) void scan_small_kernel(int nb)
{
    __shared__ int sm[128];
    int v = (threadIdx.x < nb) ? g_bsums[threadIdx.x] : 0;
    sm[threadIdx.x] = v;
    __syncthreads();
    #pragma unroll
    for (int off = 1; off < 128; off <<= 1) {
        int t = (threadIdx.x >= off) ? sm[threadIdx.x - off] : 0;
        __syncthreads();
        sm[threadIdx.x] += t;
        __syncthreads();
    }
    if (threadIdx.x < nb) g_bsums[threadIdx.x] = sm[threadIdx.x] - v;
}

__global__ void scan_add_kernel(int n, int E)
{
    int i = blockIdx.x * blockDim.x + threadIdx.x;
    if (i < n) {
        int s = g_start[i] + g_bsums[i >> 10];
        g_start[i]  = s;
        g_cursor[i] = s;
    }
    if (i == 0) g_start[n] = E;
}

__global__ void permute_kernel(const int* __restrict__ erow,
                               const int* __restrict__ ecol,
                               const float* __restrict__ eval, int E)
{
    int i = blockIdx.x * blockDim.x + threadIdx.x;
    if (i < E) {
        int r   = erow[i];
        int pos = atomicAdd(&g_cursor[r], 1);
        g_edges[pos] = make_uint2((unsigned)ecol[i], __float_as_uint(eval[i]));
    }
}

// ---------------------------------------------------------------------------
// Gather: one warp per output row, lane owns 4 features (uint2 = 4 fp16).
// out[r] = relu( sum_e val_e * support_h[col_e] ). fp32 accumulate.
// ---------------------------------------------------------------------------
__global__ __launch_bounds__(256) void gather_kernel(float* __restrict__ out)
{
    int row  = (blockIdx.x * blockDim.x + threadIdx.x) >> 5;
    int lane = threadIdx.x & 31;
    if (row >= M_NODES) return;

    int s = g_start[row];
    int e = g_start[row + 1];

    const uint2* sup = (const uint2*)g_support_h;   // 32 uint2 per node row

    float4 acc0 = make_float4(0.f, 0.f, 0.f, 0.f);
    float4 acc1 = make_float4(0.f, 0.f, 0.f, 0.f);

    for (int base = s; base < e; base += 32) {
        int m = min(32, e - base);
        uint2 ed = (base + lane < e) ? g_edges[base + lane] : make_uint2(0u, 0u);

        int j = 0;
        for (; j + 2 <= m; j += 2) {
            unsigned c0 = __shfl_sync(0xffffffffu, ed.x, j);
            float    v0 = __uint_as_float(__shfl_sync(0xffffffffu, ed.y, j));
            unsigned c1 = __shfl_sync(0xffffffffu, ed.x, j + 1);
            float    v1 = __uint_as_float(__shfl_sync(0xffffffffu, ed.y, j + 1));
            uint2 d0 = sup[(size_t)c0 * 32 + lane];
            uint2 d1 = sup[(size_t)c1 * 32 + lane];
            {
                float2 f0 = __half22float2(*(__half2*)&d0.x);
                float2 f1 = __half22float2(*(__half2*)&d0.y);
                acc0.x += v0 * f0.x; acc0.y += v0 * f0.y;
                acc0.z += v0 * f1.x; acc0.w += v0 * f1.y;
            }
            {
                float2 f0 = __half22float2(*(__half2*)&d1.x);
                float2 f1 = __half22float2(*(__half2*)&d1.y);
                acc1.x += v1 * f0.x; acc1.y += v1 * f0.y;
                acc1.z += v1 * f1.x; acc1.w += v1 * f1.y;
            }
        }
        if (j < m) {
            unsigned c0 = __shfl_sync(0xffffffffu, ed.x, j);
            float    v0 = __uint_as_float(__shfl_sync(0xffffffffu, ed.y, j));
            uint2 d0 = sup[(size_t)c0 * 32 + lane];
            float2 f0 = __half22float2(*(__half2*)&d0.x);
            float2 f1 = __half22float2(*(__half2*)&d0.y);
            acc0.x += v0 * f0.x; acc0.y += v0 * f0.y;
            acc0.z += v0 * f1.x; acc0.w += v0 * f1.y;
        }
    }

    float4 o;
    o.x = fmaxf(acc0.x + acc1.x, 0.f);
    o.y = fmaxf(acc0.y + acc1.y, 0.f);
    o.z = fmaxf(acc0.z + acc1.z, 0.f);
    o.w = fmaxf(acc0.w + acc1.w, 0.f);
    __stcs((float4*)(out + (size_t)row * N_OUT) + lane, o);
}

// ---------------------------------------------------------------------------
extern "C" void kernel_launch(void* const* d_in, const int* in_sizes, int n_in,
                              void* d_out, int out_size)
{
    const float* x    = (const float*)d_in[0];
    const int*   erow = (const int*)  d_in[1];
    const int*   ecol = (const int*)  d_in[2];
    const float* eval = (const float*)d_in[3];
    const float* W    = (const float*)d_in[4];
    const float* bias = (const float*)d_in[5];
    float* out = (float*)d_out;

    const int E = in_sizes[1];

    // 1) support = x @ W + b  (TF32 tensor cores, double-buffered)
    const int GEMM_SMEM = (2 * 128 * 36 + 2 * 32 * 136) * 4;   // 71680 B
    cudaFuncSetAttribute(gemm_tf32_kernel,
                         cudaFuncAttributeMaxDynamicSharedMemorySize, GEMM_SMEM);
    gemm_tf32_kernel<<<(M_NODES + 127) / 128, 256, GEMM_SMEM>>>(x, W, bias);

    // 2) CSR build
    zero_cnt_kernel<<<(M_NODES + 255) / 256, 256>>>(M_NODES);
    hist_kernel<<<(E + 255) / 256, 256>>>(erow, E);
    int nb = (M_NODES + SCAN_BS - 1) / SCAN_BS;
    scan_blocks_kernel<<<nb, SCAN_BS>>>(M_NODES);
    scan_small_kernel<<<1, 128>>>(nb);
    scan_add_kernel<<<(M_NODES + 255) / 256, 256>>>(M_NODES, E);
    permute_kernel<<<(E + 255) / 256, 256>>>(erow, ecol, eval, E);

    // 3) fused gather + ReLU (atomic-free, fp16 support, fp32 accumulate)
    gather_kernel<<<(M_NODES * 32 + 255) / 256, 256>>>(out);
}

// round 5
// speedup vs baseline: 2.5103x; 1.0510x over previous
#include <cuda_runtime.h>
#include <cuda_fp16.h>
#include <cstdint>

#define M_NODES 100000
#define K_IN    256
#define N_OUT   128
#define MAX_E   1600000
#define SCAN_BS 1024

// ---- static device scratch (no allocs allowed) ----
__device__ __half g_support_h[(size_t)M_NODES * N_OUT];   // 25.6 MB, fp16
__device__ int    g_cnt[M_NODES];
__device__ int    g_start[M_NODES + 1];
__device__ int    g_cursor[M_NODES];
__device__ int    g_bsums[128];
__device__ uint2  g_edges[MAX_E];                         // packed (col, val_bits)

__device__ __forceinline__ uint32_t f2tf(float f)
{
    uint32_t u;
    asm("cvt.rna.tf32.f32 %0, %1;" : "=r"(u) : "f"(f));
    return u;
}

// ---------------------------------------------------------------------------
// Kernel 1: support = x @ W + b   via TF32 mma.sync.m16n8k8
// Double-buffered smem with register prefetch (unchanged from round 4).
// ---------------------------------------------------------------------------
__global__ __launch_bounds__(256) void gemm_tf32_kernel(
    const float* __restrict__ x,
    const float* __restrict__ W,
    const float* __restrict__ bias)
{
    extern __shared__ uint32_t smbuf[];
    uint32_t* AsBase = smbuf;                    // [2][128][36]
    uint32_t* BsBase = smbuf + 2 * 128 * 36;     // [2][32][136]

    const int tid   = threadIdx.x;
    const int lane  = tid & 31;
    const int wid   = tid >> 5;
    const int warpM = wid & 3;
    const int warpN = wid >> 2;
    const int g     = lane >> 2;
    const int tg    = lane & 3;
    const int rowBase = blockIdx.x * 128;

    float acc[2][8][4];
    #pragma unroll
    for (int mt = 0; mt < 2; mt++)
        #pragma unroll
        for (int nt = 0; nt < 8; nt++)
            #pragma unroll
            for (int r = 0; r < 4; r++) acc[mt][nt][r] = 0.f;

    float4 ar[4], br[4];

    auto loadTiles = [&](int kb) {
        #pragma unroll
        for (int i = 0; i < 4; i++) {
            int idx  = tid + i * 256;
            int row  = idx >> 3;
            int k4   = (idx & 7) * 4;
            int grow = rowBase + row;
            ar[i] = (grow < M_NODES)
                  ? *(const float4*)(x + (size_t)grow * K_IN + kb + k4)
                  : make_float4(0.f, 0.f, 0.f, 0.f);
        }
        #pragma unroll
        for (int i = 0; i < 4; i++) {
            int idx  = tid + i * 256;
            int krow = idx >> 5;
            int n4   = (idx & 31) * 4;
            br[i] = *(const float4*)(W + (size_t)(kb + krow) * N_OUT + n4);
        }
    };

    auto storeTiles = [&](int s) {
        uint32_t* A = AsBase + s * 128 * 36;
        uint32_t* B = BsBase + s * 32 * 136;
        #pragma unroll
        for (int i = 0; i < 4; i++) {
            int idx = tid + i * 256;
            int row = idx >> 3;
            int k4  = (idx & 7) * 4;
            A[row * 36 + k4 + 0] = f2tf(ar[i].x);
            A[row * 36 + k4 + 1] = f2tf(ar[i].y);
            A[row * 36 + k4 + 2] = f2tf(ar[i].z);
            A[row * 36 + k4 + 3] = f2tf(ar[i].w);
        }
        #pragma unroll
        for (int i = 0; i < 4; i++) {
            int idx  = tid + i * 256;
            int krow = idx >> 5;
            int n4   = (idx & 31) * 4;
            B[krow * 136 + n4 + 0] = f2tf(br[i].x);
            B[krow * 136 + n4 + 1] = f2tf(br[i].y);
            B[krow * 136 + n4 + 2] = f2tf(br[i].z);
            B[krow * 136 + n4 + 3] = f2tf(br[i].w);
        }
    };

    auto compute = [&](int s) {
        const uint32_t* A = AsBase + s * 128 * 36;
        const uint32_t* B = BsBase + s * 32 * 136;
        #pragma unroll
        for (int ks = 0; ks < 4; ks++) {
            const int kk = ks * 8;
            uint32_t bfr[8][2];
            #pragma unroll
            for (int nt = 0; nt < 8; nt++) {
                int col = warpN * 64 + nt * 8 + g;
                bfr[nt][0] = B[(kk + tg) * 136 + col];
                bfr[nt][1] = B[(kk + tg + 4) * 136 + col];
            }
            #pragma unroll
            for (int mt = 0; mt < 2; mt++) {
                int r0 = warpM * 32 + mt * 16 + g;
                uint32_t a0 = A[r0 * 36 + kk + tg];
                uint32_t a1 = A[(r0 + 8) * 36 + kk + tg];
                uint32_t a2 = A[r0 * 36 + kk + tg + 4];
                uint32_t a3 = A[(r0 + 8) * 36 + kk + tg + 4];
                #pragma unroll
                for (int nt = 0; nt < 8; nt++) {
                    asm volatile(
                        "mma.sync.aligned.m16n8k8.row.col.f32.tf32.tf32.f32 "
                        "{%0,%1,%2,%3}, {%4,%5,%6,%7}, {%8,%9}, {%0,%1,%2,%3};"
                        : "+f"(acc[mt][nt][0]), "+f"(acc[mt][nt][1]),
                          "+f"(acc[mt][nt][2]), "+f"(acc[mt][nt][3])
                        : "r"(a0), "r"(a1), "r"(a2), "r"(a3),
                          "r"(bfr[nt][0]), "r"(bfr[nt][1]));
                }
            }
        }
    };

    loadTiles(0);
    storeTiles(0);
    __syncthreads();

    #pragma unroll
    for (int kb = 0; kb < 8; kb++) {
        int cur = kb & 1;
        if (kb < 7) loadTiles((kb + 1) * 32);
        compute(cur);
        if (kb < 7) {
            storeTiles(cur ^ 1);
            __syncthreads();
        }
    }

    #pragma unroll
    for (int nt = 0; nt < 8; nt++) {
        int col = warpN * 64 + nt * 8 + tg * 2;
        float2 bv = *(const float2*)(bias + col);
        #pragma unroll
        for (int mt = 0; mt < 2; mt++) {
            int row0 = rowBase + warpM * 32 + mt * 16 + g;
            if (row0 < M_NODES) {
                __half2 h = __floats2half2_rn(acc[mt][nt][0] + bv.x,
                                              acc[mt][nt][1] + bv.y);
                *(__half2*)(g_support_h + (size_t)row0 * N_OUT + col) = h;
            }
            int row1 = row0 + 8;
            if (row1 < M_NODES) {
                __half2 h = __floats2half2_rn(acc[mt][nt][2] + bv.x,
                                              acc[mt][nt][3] + bv.y);
                *(__half2*)(g_support_h + (size_t)row1 * N_OUT + col) = h;
            }
        }
    }
}

// ---------------------------------------------------------------------------
// CSR build: histogram -> scan -> permute
// ---------------------------------------------------------------------------
__global__ void zero_cnt_kernel(int n)
{
    int i = blockIdx.x * blockDim.x + threadIdx.x;
    if (i < n) g_cnt[i] = 0;
}

__global__ void hist_kernel(const int* __restrict__ erow, int E)
{
    int i = blockIdx.x * blockDim.x + threadIdx.x;
    if (i < E) atomicAdd(&g_cnt[erow[i]], 1);
}

__global__ __launch_bounds__(SCAN_BS) void scan_blocks_kernel(int n)
{
    __shared__ int sm[SCAN_BS];
    int i = blockIdx.x * SCAN_BS + threadIdx.x;
    int v = (i < n) ? g_cnt[i] : 0;
    sm[threadIdx.x] = v;
    __syncthreads();
    #pragma unroll
    for (int off = 1; off < SCAN_BS; off <<= 1) {
        int t = (threadIdx.x >= off) ? sm[threadIdx.x - off] : 0;
        __syncthreads();
        sm[threadIdx.x] += t;
        __syncthreads();
    }
    if (i < n) g_start[i] = sm[threadIdx.x] - v;
    if (threadIdx.x == SCAN_BS - 1) g_bsums[blockIdx.x] = sm[SCAN_BS - 1];
}

__global__ __launch_bounds__(128) void scan_small_kernel(int nb)
{
    __shared__ int sm[128];
    int v = (threadIdx.x < nb) ? g_bsums[threadIdx.x] : 0;
    sm[threadIdx.x] = v;
    __syncthreads();
    #pragma unroll
    for (int off = 1; off < 128; off <<= 1) {
        int t = (threadIdx.x >= off) ? sm[threadIdx.x - off] : 0;
        __syncthreads();
        sm[threadIdx.x] += t;
        __syncthreads();
    }
    if (threadIdx.x < nb) g_bsums[threadIdx.x] = sm[threadIdx.x] - v;
}

__global__ void scan_add_kernel(int n, int E)
{
    int i = blockIdx.x * blockDim.x + threadIdx.x;
    if (i < n) {
        int s = g_start[i] + g_bsums[i >> 10];
        g_start[i]  = s;
        g_cursor[i] = s;
    }
    if (i == 0) g_start[n] = E;
}

__global__ void permute_kernel(const int* __restrict__ erow,
                               const int* __restrict__ ecol,
                               const float* __restrict__ eval, int E)
{
    int i = blockIdx.x * blockDim.x + threadIdx.x;
    if (i < E) {
        int r   = erow[i];
        int pos = atomicAdd(&g_cursor[r], 1);
        g_edges[pos] = make_uint2((unsigned)ecol[i], __float_as_uint(eval[i]));
    }
}

// ---------------------------------------------------------------------------
// Gather: one warp per output row, lane owns 4 features (uint2 = 4 fp16).
// Edge records are read by ALL lanes at the same address -> HW broadcast,
// no SHFLs. Unroll 4 edges/iter: 4 independent support-row loads in flight.
// ---------------------------------------------------------------------------
__global__ __launch_bounds__(256) void gather_kernel(float* __restrict__ out)
{
    int row  = (blockIdx.x * blockDim.x + threadIdx.x) >> 5;
    int lane = threadIdx.x & 31;
    if (row >= M_NODES) return;

    int s = g_start[row];
    int e = g_start[row + 1];

    const uint2* sup = (const uint2*)g_support_h;   // 32 uint2 per node row

    float4 acc0 = make_float4(0.f, 0.f, 0.f, 0.f);
    float4 acc1 = make_float4(0.f, 0.f, 0.f, 0.f);

    int j = s;
    for (; j + 4 <= e; j += 4) {
        // uniform loads (broadcast across the warp)
        uint2 e0 = __ldg(&g_edges[j + 0]);
        uint2 e1 = __ldg(&g_edges[j + 1]);
        uint2 e2 = __ldg(&g_edges[j + 2]);
        uint2 e3 = __ldg(&g_edges[j + 3]);
        // 4 independent gathers in flight
        uint2 d0 = __ldg(&sup[(size_t)e0.x * 32 + lane]);
        uint2 d1 = __ldg(&sup[(size_t)e1.x * 32 + lane]);
        uint2 d2 = __ldg(&sup[(size_t)e2.x * 32 + lane]);
        uint2 d3 = __ldg(&sup[(size_t)e3.x * 32 + lane]);

        float v0 = __uint_as_float(e0.y);
        float v1 = __uint_as_float(e1.y);
        float v2 = __uint_as_float(e2.y);
        float v3 = __uint_as_float(e3.y);

        float2 a, b;
        a = __half22float2(*(__half2*)&d0.x); b = __half22float2(*(__half2*)&d0.y);
        acc0.x += v0 * a.x; acc0.y += v0 * a.y; acc0.z += v0 * b.x; acc0.w += v0 * b.y;
        a = __half22float2(*(__half2*)&d1.x); b = __half22float2(*(__half2*)&d1.y);
        acc1.x += v1 * a.x; acc1.y += v1 * a.y; acc1.z += v1 * b.x; acc1.w += v1 * b.y;
        a = __half22float2(*(__half2*)&d2.x); b = __half22float2(*(__half2*)&d2.y);
        acc0.x += v2 * a.x; acc0.y += v2 * a.y; acc0.z += v2 * b.x; acc0.w += v2 * b.y;
        a = __half22float2(*(__half2*)&d3.x); b = __half22float2(*(__half2*)&d3.y);
        acc1.x += v3 * a.x; acc1.y += v3 * a.y; acc1.z += v3 * b.x; acc1.w += v3 * b.y;
    }
    for (; j < e; j++) {
        uint2 e0 = __ldg(&g_edges[j]);
        uint2 d0 = __ldg(&sup[(size_t)e0.x * 32 + lane]);
        float v0 = __uint_as_float(e0.y);
        float2 a = __half22float2(*(__half2*)&d0.x);
        float2 b = __half22float2(*(__half2*)&d0.y);
        acc0.x += v0 * a.x; acc0.y += v0 * a.y; acc0.z += v0 * b.x; acc0.w += v0 * b.y;
    }

    float4 o;
    o.x = fmaxf(acc0.x + acc1.x, 0.f);
    o.y = fmaxf(acc0.y + acc1.y, 0.f);
    o.z = fmaxf(acc0.z + acc1.z, 0.f);
    o.w = fmaxf(acc0.w + acc1.w, 0.f);
    __stcs((float4*)(out + (size_t)row * N_OUT) + lane, o);
}

// ---------------------------------------------------------------------------
extern "C" void kernel_launch(void* const* d_in, const int* in_sizes, int n_in,
                              void* d_out, int out_size)
{
    const float* x    = (const float*)d_in[0];
    const int*   erow = (const int*)  d_in[1];
    const int*   ecol = (const int*)  d_in[2];
    const float* eval = (const float*)d_in[3];
    const float* W    = (const float*)d_in[4];
    const float* bias = (const float*)d_in[5];
    float* out = (float*)d_out;

    const int E = in_sizes[1];

    // 1) support = x @ W + b  (TF32 tensor cores, double-buffered)
    const int GEMM_SMEM = (2 * 128 * 36 + 2 * 32 * 136) * 4;   // 71680 B
    cudaFuncSetAttribute(gemm_tf32_kernel,
                         cudaFuncAttributeMaxDynamicSharedMemorySize, GEMM_SMEM);
    gemm_tf32_kernel<<<(M_NODES + 127) / 128, 256, GEMM_SMEM>>>(x, W, bias);

    // 2) CSR build
    zero_cnt_kernel<<<(M_NODES + 255) / 256, 256>>>(M_NODES);
    hist_kernel<<<(E + 255) / 256, 256>>>(erow, E);
    int nb = (M_NODES + SCAN_BS - 1) / SCAN_BS;
    scan_blocks_kernel<<<nb, SCAN_BS>>>(M_NODES);
    scan_small_kernel<<<1, 128>>>(nb);
    scan_add_kernel<<<(M_NODES + 255) / 256, 256>>>(M_NODES, E);
    permute_kernel<<<(E + 255) / 256, 256>>>(erow, ecol, eval, E);

    // 3) fused gather + ReLU (atomic-free, uniform edge loads, MLP=4)
    gather_kernel<<<(M_NODES * 32 + 255) / 256, 256>>>(out);
}

// round 6
// speedup vs baseline: 2.8365x; 1.1299x over previous
#include <cuda_runtime.h>
#include <cuda_fp16.h>
#include <cstdint>

#define M_NODES 100000
#define K_IN    256
#define N_OUT   128
#define MAX_E   1600000
#define SCAN_BS 1024

// ---- static device scratch (no allocs allowed) ----
__device__ __half    g_support_h[(size_t)M_NODES * N_OUT];  // 25.6 MB fp16
__device__ uint32_t  g_Wtf[K_IN * N_OUT];                   // W pre-converted to tf32
__device__ int       g_cnt[M_NODES];
__device__ int       g_start[M_NODES + 1];
__device__ int       g_cursor[M_NODES];
__device__ int       g_bsums[128];
__device__ uint2     g_edges[MAX_E];                        // packed (col, val_bits)

__device__ __forceinline__ uint32_t f2tf(float f)
{
    uint32_t u;
    asm("cvt.rna.tf32.f32 %0, %1;" : "=r"(u) : "f"(f));
    return u;
}

__device__ __forceinline__ void cp_async16(uint32_t saddr, const void* gptr, int srcBytes)
{
    asm volatile("cp.async.cg.shared.global [%0], [%1], 16, %2;\n"
                 :: "r"(saddr), "l"(gptr), "r"(srcBytes));
}
#define CP_COMMIT() asm volatile("cp.async.commit_group;\n" ::)
#define CP_WAIT0()  asm volatile("cp.async.wait_group 0;\n" ::)

// ---------------------------------------------------------------------------
// Kernel 0: W -> tf32 (tiny, runs once per launch)
// ---------------------------------------------------------------------------
__global__ void wconv_kernel(const float* __restrict__ W)
{
    int i = blockIdx.x * blockDim.x + threadIdx.x;
    if (i < K_IN * N_OUT) g_Wtf[i] = f2tf(W[i]);
}

// ---------------------------------------------------------------------------
// Kernel 1: support = x @ W + b  via TF32 mma.sync.m16n8k8
// True async pipeline: cp.async double-buffered tiles, compute overlaps loads.
// A staged as raw fp32, cvt.rna at fragment load (identical rounding to r5).
// B staged pre-converted tf32.  Smem strides keep LDS bank-bijective.
// ---------------------------------------------------------------------------
__global__ __launch_bounds__(256) void gemm_tf32_kernel(
    const float* __restrict__ x,
    const float* __restrict__ bias)
{
    extern __shared__ float smf[];
    float*    Asf = smf;                              // [2][128][36] raw fp32
    uint32_t* Bsf = (uint32_t*)(smf + 2 * 128 * 36);  // [2][32][136] tf32

    const int tid   = threadIdx.x;
    const int lane  = tid & 31;
    const int wid   = tid >> 5;
    const int warpM = wid & 3;
    const int warpN = wid >> 2;
    const int g     = lane >> 2;
    const int tg    = lane & 3;
    const int rowBase = blockIdx.x * 128;

    float acc[2][8][4];
    #pragma unroll
    for (int mt = 0; mt < 2; mt++)
        #pragma unroll
        for (int nt = 0; nt < 8; nt++)
            #pragma unroll
            for (int r = 0; r < 4; r++) acc[mt][nt][r] = 0.f;

    const uint32_t aBase[2] = {
        (uint32_t)__cvta_generic_to_shared(Asf),
        (uint32_t)__cvta_generic_to_shared(Asf + 128 * 36) };
    const uint32_t bBase[2] = {
        (uint32_t)__cvta_generic_to_shared(Bsf),
        (uint32_t)__cvta_generic_to_shared(Bsf + 32 * 136) };

    auto loadStage = [&](int kb, int s) {
        // A tile: 128 rows x 32 k = 1024 x 16B chunks, 4 per thread
        #pragma unroll
        for (int i = 0; i < 4; i++) {
            int idx  = tid + i * 256;
            int row  = idx >> 3;
            int k4   = (idx & 7) * 4;
            int grow = rowBase + row;
            int sz   = (grow < M_NODES) ? 16 : 0;
            const float* src = x + (size_t)min(grow, M_NODES - 1) * K_IN + kb + k4;
            cp_async16(aBase[s] + (uint32_t)(row * 36 + k4) * 4, src, sz);
        }
        // B tile: 32 k x 128 n = 1024 x 16B chunks, 4 per thread (tf32 already)
        #pragma unroll
        for (int i = 0; i < 4; i++) {
            int idx  = tid + i * 256;
            int krow = idx >> 5;
            int n4   = (idx & 31) * 4;
            cp_async16(bBase[s] + (uint32_t)(krow * 136 + n4) * 4,
                       g_Wtf + (kb + krow) * N_OUT + n4, 16);
        }
        CP_COMMIT();
    };

    auto compute = [&](int s) {
        const float*    A = Asf + s * 128 * 36;
        const uint32_t* B = Bsf + s * 32 * 136;
        #pragma unroll
        for (int ks = 0; ks < 4; ks++) {
            const int kk = ks * 8;
            uint32_t bfr[8][2];
            #pragma unroll
            for (int nt = 0; nt < 8; nt++) {
                int col = warpN * 64 + nt * 8 + g;
                bfr[nt][0] = B[(kk + tg) * 136 + col];
                bfr[nt][1] = B[(kk + tg + 4) * 136 + col];
            }
            #pragma unroll
            for (int mt = 0; mt < 2; mt++) {
                int r0 = warpM * 32 + mt * 16 + g;
                uint32_t a0 = f2tf(A[r0 * 36 + kk + tg]);
                uint32_t a1 = f2tf(A[(r0 + 8) * 36 + kk + tg]);
                uint32_t a2 = f2tf(A[r0 * 36 + kk + tg + 4]);
                uint32_t a3 = f2tf(A[(r0 + 8) * 36 + kk + tg + 4]);
                #pragma unroll
                for (int nt = 0; nt < 8; nt++) {
                    asm volatile(
                        "mma.sync.aligned.m16n8k8.row.col.f32.tf32.tf32.f32 "
                        "{%0,%1,%2,%3}, {%4,%5,%6,%7}, {%8,%9}, {%0,%1,%2,%3};"
                        : "+f"(acc[mt][nt][0]), "+f"(acc[mt][nt][1]),
                          "+f"(acc[mt][nt][2]), "+f"(acc[mt][nt][3])
                        : "r"(a0), "r"(a1), "r"(a2), "r"(a3),
                          "r"(bfr[nt][0]), "r"(bfr[nt][1]));
                }
            }
        }
    };

    loadStage(0, 0);
    CP_WAIT0();
    __syncthreads();

    #pragma unroll
    for (int kb = 0; kb < 8; kb++) {
        if (kb < 7) loadStage((kb + 1) * 32, (kb + 1) & 1);  // overlaps compute
        compute(kb & 1);
        if (kb < 7) {
            CP_WAIT0();
            __syncthreads();
        }
    }

    // ---- epilogue: += bias, pack fp16, store ----
    #pragma unroll
    for (int nt = 0; nt < 8; nt++) {
        int col = warpN * 64 + nt * 8 + tg * 2;
        float2 bv = *(const float2*)(bias + col);
        #pragma unroll
        for (int mt = 0; mt < 2; mt++) {
            int row0 = rowBase + warpM * 32 + mt * 16 + g;
            if (row0 < M_NODES) {
                __half2 h = __floats2half2_rn(acc[mt][nt][0] + bv.x,
                                              acc[mt][nt][1] + bv.y);
                *(__half2*)(g_support_h + (size_t)row0 * N_OUT + col) = h;
            }
            int row1 = row0 + 8;
            if (row1 < M_NODES) {
                __half2 h = __floats2half2_rn(acc[mt][nt][2] + bv.x,
                                              acc[mt][nt][3] + bv.y);
                *(__half2*)(g_support_h + (size_t)row1 * N_OUT + col) = h;
            }
        }
    }
}

// ---------------------------------------------------------------------------
// CSR build: histogram -> scan (self-cleaning) -> permute
// ---------------------------------------------------------------------------
__global__ void hist_kernel(const int* __restrict__ erow, int E)
{
    int i = blockIdx.x * blockDim.x + threadIdx.x;
    if (i < E) atomicAdd(&g_cnt[erow[i]], 1);
}

__global__ __launch_bounds__(SCAN_BS) void scan_blocks_kernel(int n)
{
    __shared__ int sm[SCAN_BS];
    int i = blockIdx.x * SCAN_BS + threadIdx.x;
    int v = (i < n) ? g_cnt[i] : 0;
    if (i < n) g_cnt[i] = 0;              // self-clean for the next replay
    sm[threadIdx.x] = v;
    __syncthreads();
    #pragma unroll
    for (int off = 1; off < SCAN_BS; off <<= 1) {
        int t = (threadIdx.x >= off) ? sm[threadIdx.x - off] : 0;
        __syncthreads();
        sm[threadIdx.x] += t;
        __syncthreads();
    }
    if (i < n) g_start[i] = sm[threadIdx.x] - v;
    if (threadIdx.x == SCAN_BS - 1) g_bsums[blockIdx.x] = sm[SCAN_BS - 1];
}

__global__ __launch_bounds__(128) void scan_small_kernel(int nb)
{
    __shared__ int sm[128];
    int v = (threadIdx.x < nb) ? g_bsums[threadIdx.x] : 0;
    sm[threadIdx.x] = v;
    __syncthreads();
    #pragma unroll
    for (int off = 1; off < 128; off <<= 1) {
        int t = (threadIdx.x >= off) ? sm[threadIdx.x - off] : 0;
        __syncthreads();
        sm[threadIdx.x] += t;
        __syncthreads();
    }
    if (threadIdx.x < nb) g_bsums[threadIdx.x] = sm[threadIdx.x] - v;
}

__global__ void scan_add_kernel(int n, int E)
{
    int i = blockIdx.x * blockDim.x + threadIdx.x;
    if (i < n) {
        int s = g_start[i] + g_bsums[i >> 10];
        g_start[i]  = s;
        g_cursor[i] = s;
    }
    if (i == 0) g_start[n] = E;
}

__global__ void permute_kernel(const int* __restrict__ erow,
                               const int* __restrict__ ecol,
                               const float* __restrict__ eval, int E)
{
    int i = blockIdx.x * blockDim.x + threadIdx.x;
    if (i < E) {
        int r   = erow[i];
        int pos = atomicAdd(&g_cursor[r], 1);
        g_edges[pos] = make_uint2((unsigned)ecol[i], __float_as_uint(eval[i]));
    }
}

// ---------------------------------------------------------------------------
// Gather: one warp per row, lane owns 4 features; uniform edge loads
// (HW broadcast), 4 independent support gathers in flight. (unchanged)
// ---------------------------------------------------------------------------
__global__ __launch_bounds__(256) void gather_kernel(float* __restrict__ out)
{
    int row  = (blockIdx.x * blockDim.x + threadIdx.x) >> 5;
    int lane = threadIdx.x & 31;
    if (row >= M_NODES) return;

    int s = g_start[row];
    int e = g_start[row + 1];

    const uint2* sup = (const uint2*)g_support_h;

    float4 acc0 = make_float4(0.f, 0.f, 0.f, 0.f);
    float4 acc1 = make_float4(0.f, 0.f, 0.f, 0.f);

    int j = s;
    for (; j + 4 <= e; j += 4) {
        uint2 e0 = __ldg(&g_edges[j + 0]);
        uint2 e1 = __ldg(&g_edges[j + 1]);
        uint2 e2 = __ldg(&g_edges[j + 2]);
        uint2 e3 = __ldg(&g_edges[j + 3]);
        uint2 d0 = __ldg(&sup[(size_t)e0.x * 32 + lane]);
        uint2 d1 = __ldg(&sup[(size_t)e1.x * 32 + lane]);
        uint2 d2 = __ldg(&sup[(size_t)e2.x * 32 + lane]);
        uint2 d3 = __ldg(&sup[(size_t)e3.x * 32 + lane]);

        float v0 = __uint_as_float(e0.y);
        float v1 = __uint_as_float(e1.y);
        float v2 = __uint_as_float(e2.y);
        float v3 = __uint_as_float(e3.y);

        float2 a, b;
        a = __half22float2(*(__half2*)&d0.x); b = __half22float2(*(__half2*)&d0.y);
        acc0.x += v0 * a.x; acc0.y += v0 * a.y; acc0.z += v0 * b.x; acc0.w += v0 * b.y;
        a = __half22float2(*(__half2*)&d1.x); b = __half22float2(*(__half2*)&d1.y);
        acc1.x += v1 * a.x; acc1.y += v1 * a.y; acc1.z += v1 * b.x; acc1.w += v1 * b.y;
        a = __half22float2(*(__half2*)&d2.x); b = __half22float2(*(__half2*)&d2.y);
        acc0.x += v2 * a.x; acc0.y += v2 * a.y; acc0.z += v2 * b.x; acc0.w += v2 * b.y;
        a = __half22float2(*(__half2*)&d3.x); b = __half22float2(*(__half2*)&d3.y);
        acc1.x += v3 * a.x; acc1.y += v3 * a.y; acc1.z += v3 * b.x; acc1.w += v3 * b.y;
    }
    for (; j < e; j++) {
        uint2 e0 = __ldg(&g_edges[j]);
        uint2 d0 = __ldg(&sup[(size_t)e0.x * 32 + lane]);
        float v0 = __uint_as_float(e0.y);
        float2 a = __half22float2(*(__half2*)&d0.x);
        float2 b = __half22float2(*(__half2*)&d0.y);
        acc0.x += v0 * a.x; acc0.y += v0 * a.y; acc0.z += v0 * b.x; acc0.w += v0 * b.y;
    }

    float4 o;
    o.x = fmaxf(acc0.x + acc1.x, 0.f);
    o.y = fmaxf(acc0.y + acc1.y, 0.f);
    o.z = fmaxf(acc0.z + acc1.z, 0.f);
    o.w = fmaxf(acc0.w + acc1.w, 0.f);
    __stcs((float4*)(out + (size_t)row * N_OUT) + lane, o);
}

// ---------------------------------------------------------------------------
extern "C" void kernel_launch(void* const* d_in, const int* in_sizes, int n_in,
                              void* d_out, int out_size)
{
    const float* x    = (const float*)d_in[0];
    const int*   erow = (const int*)  d_in[1];
    const int*   ecol = (const int*)  d_in[2];
    const float* eval = (const float*)d_in[3];
    const float* W    = (const float*)d_in[4];
    const float* bias = (const float*)d_in[5];
    float* out = (float*)d_out;

    const int E = in_sizes[1];

    // 0) W -> tf32
    wconv_kernel<<<(K_IN * N_OUT + 255) / 256, 256>>>(W);

    // 1) support = x @ W + b  (cp.async double-buffered TF32 GEMM)
    const int GEMM_SMEM = (2 * 128 * 36 + 2 * 32 * 136) * 4;   // 71680 B
    cudaFuncSetAttribute(gemm_tf32_kernel,
                         cudaFuncAttributeMaxDynamicSharedMemorySize, GEMM_SMEM);
    gemm_tf32_kernel<<<(M_NODES + 127) / 128, 256, GEMM_SMEM>>>(x, bias);

    // 2) CSR build (g_cnt self-cleaned by scan_blocks)
    hist_kernel<<<(E + 255) / 256, 256>>>(erow, E);
    int nb = (M_NODES + SCAN_BS - 1) / SCAN_BS;
    scan_blocks_kernel<<<nb, SCAN_BS>>>(M_NODES);
    scan_small_kernel<<<1, 128>>>(nb);
    scan_add_kernel<<<(M_NODES + 255) / 256, 256>>>(M_NODES, E);
    permute_kernel<<<(E + 255) / 256, 256>>>(erow, ecol, eval, E);

    // 3) fused gather + ReLU
    gather_kernel<<<(M_NODES * 32 + 255) / 256, 256>>>(out);
}

// round 7
// speedup vs baseline: 2.9712x; 1.0475x over previous
#include <cuda_runtime.h>
#include <cuda_fp16.h>
#include <cstdint>

#define M_NODES 100000
#define K_IN    256
#define N_OUT   128
#define MAX_E   1600000
#define SCAN_BS 1024

// ---- static device scratch (no allocs allowed) ----
__device__ __half    g_support_h[(size_t)M_NODES * N_OUT];  // 25.6 MB fp16
__device__ uint32_t  g_Wtf[K_IN * N_OUT];                   // W pre-converted to tf32
__device__ int       g_cnt[M_NODES];
__device__ int       g_start[M_NODES + 1];
__device__ int       g_cursor[M_NODES];
__device__ int       g_bsums[128];
__device__ uint2     g_edges[MAX_E];                        // packed (col, val_bits)

__device__ __forceinline__ uint32_t f2tf(float f)
{
    uint32_t u;
    asm("cvt.rna.tf32.f32 %0, %1;" : "=r"(u) : "f"(f));
    return u;
}

__device__ __forceinline__ void cp_async16(uint32_t saddr, const void* gptr, int srcBytes)
{
    asm volatile("cp.async.cg.shared.global [%0], [%1], 16, %2;\n"
                 :: "r"(saddr), "l"(gptr), "r"(srcBytes));
}
#define CP_COMMIT() asm volatile("cp.async.commit_group;\n" ::)
#define CP_WAIT0()  asm volatile("cp.async.wait_group 0;\n" ::)

// ---------------------------------------------------------------------------
// Kernel 0: W -> tf32 (tiny)
// ---------------------------------------------------------------------------
__global__ void wconv_kernel(const float* __restrict__ W)
{
    int i = blockIdx.x * blockDim.x + threadIdx.x;
    if (i < K_IN * N_OUT) g_Wtf[i] = f2tf(W[i]);
}

// ---------------------------------------------------------------------------
// Kernel 1: support = x @ W + b  via TF32 mma.sync.m16n8k8  (cp.async pipe)
// ---------------------------------------------------------------------------
__global__ __launch_bounds__(256) void gemm_tf32_kernel(
    const float* __restrict__ x,
    const float* __restrict__ bias)
{
    extern __shared__ float smf[];
    float*    Asf = smf;                              // [2][128][36] raw fp32
    uint32_t* Bsf = (uint32_t*)(smf + 2 * 128 * 36);  // [2][32][136] tf32

    const int tid   = threadIdx.x;
    const int lane  = tid & 31;
    const int wid   = tid >> 5;
    const int warpM = wid & 3;
    const int warpN = wid >> 2;
    const int g     = lane >> 2;
    const int tg    = lane & 3;
    const int rowBase = blockIdx.x * 128;

    float acc[2][8][4];
    #pragma unroll
    for (int mt = 0; mt < 2; mt++)
        #pragma unroll
        for (int nt = 0; nt < 8; nt++)
            #pragma unroll
            for (int r = 0; r < 4; r++) acc[mt][nt][r] = 0.f;

    const uint32_t aBase[2] = {
        (uint32_t)__cvta_generic_to_shared(Asf),
        (uint32_t)__cvta_generic_to_shared(Asf + 128 * 36) };
    const uint32_t bBase[2] = {
        (uint32_t)__cvta_generic_to_shared(Bsf),
        (uint32_t)__cvta_generic_to_shared(Bsf + 32 * 136) };

    auto loadStage = [&](int kb, int s) {
        #pragma unroll
        for (int i = 0; i < 4; i++) {
            int idx  = tid + i * 256;
            int row  = idx >> 3;
            int k4   = (idx & 7) * 4;
            int grow = rowBase + row;
            int sz   = (grow < M_NODES) ? 16 : 0;
            const float* src = x + (size_t)min(grow, M_NODES - 1) * K_IN + kb + k4;
            cp_async16(aBase[s] + (uint32_t)(row * 36 + k4) * 4, src, sz);
        }
        #pragma unroll
        for (int i = 0; i < 4; i++) {
            int idx  = tid + i * 256;
            int krow = idx >> 5;
            int n4   = (idx & 31) * 4;
            cp_async16(bBase[s] + (uint32_t)(krow * 136 + n4) * 4,
                       g_Wtf + (kb + krow) * N_OUT + n4, 16);
        }
        CP_COMMIT();
    };

    auto compute = [&](int s) {
        const float*    A = Asf + s * 128 * 36;
        const uint32_t* B = Bsf + s * 32 * 136;
        #pragma unroll
        for (int ks = 0; ks < 4; ks++) {
            const int kk = ks * 8;
            uint32_t bfr[8][2];
            #pragma unroll
            for (int nt = 0; nt < 8; nt++) {
                int col = warpN * 64 + nt * 8 + g;
                bfr[nt][0] = B[(kk + tg) * 136 + col];
                bfr[nt][1] = B[(kk + tg + 4) * 136 + col];
            }
            #pragma unroll
            for (int mt = 0; mt < 2; mt++) {
                int r0 = warpM * 32 + mt * 16 + g;
                uint32_t a0 = f2tf(A[r0 * 36 + kk + tg]);
                uint32_t a1 = f2tf(A[(r0 + 8) * 36 + kk + tg]);
                uint32_t a2 = f2tf(A[r0 * 36 + kk + tg + 4]);
                uint32_t a3 = f2tf(A[(r0 + 8) * 36 + kk + tg + 4]);
                #pragma unroll
                for (int nt = 0; nt < 8; nt++) {
                    asm volatile(
                        "mma.sync.aligned.m16n8k8.row.col.f32.tf32.tf32.f32 "
                        "{%0,%1,%2,%3}, {%4,%5,%6,%7}, {%8,%9}, {%0,%1,%2,%3};"
                        : "+f"(acc[mt][nt][0]), "+f"(acc[mt][nt][1]),
                          "+f"(acc[mt][nt][2]), "+f"(acc[mt][nt][3])
                        : "r"(a0), "r"(a1), "r"(a2), "r"(a3),
                          "r"(bfr[nt][0]), "r"(bfr[nt][1]));
                }
            }
        }
    };

    loadStage(0, 0);
    CP_WAIT0();
    __syncthreads();

    #pragma unroll
    for (int kb = 0; kb < 8; kb++) {
        if (kb < 7) loadStage((kb + 1) * 32, (kb + 1) & 1);
        compute(kb & 1);
        if (kb < 7) {
            CP_WAIT0();
            __syncthreads();
        }
    }

    #pragma unroll
    for (int nt = 0; nt < 8; nt++) {
        int col = warpN * 64 + nt * 8 + tg * 2;
        float2 bv = *(const float2*)(bias + col);
        #pragma unroll
        for (int mt = 0; mt < 2; mt++) {
            int row0 = rowBase + warpM * 32 + mt * 16 + g;
            if (row0 < M_NODES) {
                __half2 h = __floats2half2_rn(acc[mt][nt][0] + bv.x,
                                              acc[mt][nt][1] + bv.y);
                *(__half2*)(g_support_h + (size_t)row0 * N_OUT + col) = h;
            }
            int row1 = row0 + 8;
            if (row1 < M_NODES) {
                __half2 h = __floats2half2_rn(acc[mt][nt][2] + bv.x,
                                              acc[mt][nt][3] + bv.y);
                *(__half2*)(g_support_h + (size_t)row1 * N_OUT + col) = h;
            }
        }
    }
}

// ---------------------------------------------------------------------------
// CSR build: histogram -> shfl-scan -> permute
// ---------------------------------------------------------------------------
__global__ void hist_kernel(const int* __restrict__ erow, int E)
{
    int i = blockIdx.x * blockDim.x + threadIdx.x;
    if (i < E) atomicAdd(&g_cnt[erow[i]], 1);
}

__device__ __forceinline__ int warp_incl_scan(int v, int lane)
{
    #pragma unroll
    for (int off = 1; off < 32; off <<= 1) {
        int t = __shfl_up_sync(0xffffffffu, v, off);
        if (lane >= off) v += t;
    }
    return v;
}

// shfl-based two-level block scan; also self-cleans g_cnt for next replay
__global__ __launch_bounds__(SCAN_BS) void scan_blocks_kernel(int n)
{
    __shared__ int wsum[32];
    int i    = blockIdx.x * SCAN_BS + threadIdx.x;
    int lane = threadIdx.x & 31;
    int w    = threadIdx.x >> 5;

    int v = (i < n) ? g_cnt[i] : 0;
    if (i < n) g_cnt[i] = 0;

    int incl = warp_incl_scan(v, lane);
    if (lane == 31) wsum[w] = incl;
    __syncthreads();
    if (w == 0) {
        int s  = wsum[lane];
        int ws = warp_incl_scan(s, lane);
        wsum[lane] = ws - s;          // exclusive warp offsets
    }
    __syncthreads();

    int excl = incl - v + wsum[w];
    if (i < n) g_start[i] = excl;
    if (threadIdx.x == SCAN_BS - 1) g_bsums[blockIdx.x] = excl + v;
}

__global__ __launch_bounds__(128) void scan_small_kernel(int nb)
{
    __shared__ int wsum[4];
    int lane = threadIdx.x & 31;
    int w    = threadIdx.x >> 5;
    int v    = (threadIdx.x < nb) ? g_bsums[threadIdx.x] : 0;
    int incl = warp_incl_scan(v, lane);
    if (lane == 31) wsum[w] = incl;
    __syncthreads();
    int off = 0;
    #pragma unroll
    for (int k = 0; k < 4; k++) if (k < w) off += wsum[k];
    if (threadIdx.x < nb) g_bsums[threadIdx.x] = incl - v + off;
}

__global__ void scan_add_kernel(int n, int E)
{
    int i = blockIdx.x * blockDim.x + threadIdx.x;
    if (i < n) {
        int s = g_start[i] + g_bsums[i >> 10];
        g_start[i]  = s;
        g_cursor[i] = s;
    }
    if (i == 0) g_start[n] = E;
}

__global__ void permute_kernel(const int* __restrict__ erow,
                               const int* __restrict__ ecol,
                               const float* __restrict__ eval, int E)
{
    int i = blockIdx.x * blockDim.x + threadIdx.x;
    if (i < E) {
        int r   = erow[i];
        int pos = atomicAdd(&g_cursor[r], 1);
        g_edges[pos] = make_uint2((unsigned)ecol[i], __float_as_uint(eval[i]));
    }
}

// ---------------------------------------------------------------------------
// Gather: one warp per row, lane owns 4 features; uniform edge loads
// (HW broadcast), 4 independent support gathers in flight.
// ---------------------------------------------------------------------------
__global__ __launch_bounds__(256) void gather_kernel(float* __restrict__ out)
{
    int row  = (blockIdx.x * blockDim.x + threadIdx.x) >> 5;
    int lane = threadIdx.x & 31;
    if (row >= M_NODES) return;

    int s = g_start[row];
    int e = g_start[row + 1];

    const uint2* sup = (const uint2*)g_support_h;

    float4 acc0 = make_float4(0.f, 0.f, 0.f, 0.f);
    float4 acc1 = make_float4(0.f, 0.f, 0.f, 0.f);

    int j = s;
    for (; j + 4 <= e; j += 4) {
        uint2 e0 = __ldg(&g_edges[j + 0]);
        uint2 e1 = __ldg(&g_edges[j + 1]);
        uint2 e2 = __ldg(&g_edges[j + 2]);
        uint2 e3 = __ldg(&g_edges[j + 3]);
        uint2 d0 = __ldg(&sup[(size_t)e0.x * 32 + lane]);
        uint2 d1 = __ldg(&sup[(size_t)e1.x * 32 + lane]);
        uint2 d2 = __ldg(&sup[(size_t)e2.x * 32 + lane]);
        uint2 d3 = __ldg(&sup[(size_t)e3.x * 32 + lane]);

        float v0 = __uint_as_float(e0.y);
        float v1 = __uint_as_float(e1.y);
        float v2 = __uint_as_float(e2.y);
        float v3 = __uint_as_float(e3.y);

        float2 a, b;
        a = __half22float2(*(__half2*)&d0.x); b = __half22float2(*(__half2*)&d0.y);
        acc0.x += v0 * a.x; acc0.y += v0 * a.y; acc0.z += v0 * b.x; acc0.w += v0 * b.y;
        a = __half22float2(*(__half2*)&d1.x); b = __half22float2(*(__half2*)&d1.y);
        acc1.x += v1 * a.x; acc1.y += v1 * a.y; acc1.z += v1 * b.x; acc1.w += v1 * b.y;
        a = __half22float2(*(__half2*)&d2.x); b = __half22float2(*(__half2*)&d2.y);
        acc0.x += v2 * a.x; acc0.y += v2 * a.y; acc0.z += v2 * b.x; acc0.w += v2 * b.y;
        a = __half22float2(*(__half2*)&d3.x); b = __half22float2(*(__half2*)&d3.y);
        acc1.x += v3 * a.x; acc1.y += v3 * a.y; acc1.z += v3 * b.x; acc1.w += v3 * b.y;
    }
    for (; j < e; j++) {
        uint2 e0 = __ldg(&g_edges[j]);
        uint2 d0 = __ldg(&sup[(size_t)e0.x * 32 + lane]);
        float v0 = __uint_as_float(e0.y);
        float2 a = __half22float2(*(__half2*)&d0.x);
        float2 b = __half22float2(*(__half2*)&d0.y);
        acc0.x += v0 * a.x; acc0.y += v0 * a.y; acc0.z += v0 * b.x; acc0.w += v0 * b.y;
    }

    float4 o;
    o.x = fmaxf(acc0.x + acc1.x, 0.f);
    o.y = fmaxf(acc0.y + acc1.y, 0.f);
    o.z = fmaxf(acc0.z + acc1.z, 0.f);
    o.w = fmaxf(acc0.w + acc1.w, 0.f);
    __stcs((float4*)(out + (size_t)row * N_OUT) + lane, o);
}

// ---------------------------------------------------------------------------
// Side stream + fork/join events, created once at load time (host objects,
// before the harness's device-memory baseline; no allocs inside kernel_launch).
// ---------------------------------------------------------------------------
static cudaStream_t g_s2   = nullptr;
static cudaEvent_t  g_fork = nullptr;
static cudaEvent_t  g_join = nullptr;
namespace {
struct StreamInit {
    StreamInit() {
        if (cudaStreamCreateWithFlags(&g_s2, cudaStreamNonBlocking) != cudaSuccess) g_s2 = nullptr;
        if (cudaEventCreateWithFlags(&g_fork, cudaEventDisableTiming) != cudaSuccess) g_fork = nullptr;
        if (cudaEventCreateWithFlags(&g_join, cudaEventDisableTiming) != cudaSuccess) g_join = nullptr;
    }
};
static StreamInit g_streamInit;
}

// ---------------------------------------------------------------------------
extern "C" void kernel_launch(void* const* d_in, const int* in_sizes, int n_in,
                              void* d_out, int out_size)
{
    const float* x    = (const float*)d_in[0];
    const int*   erow = (const int*)  d_in[1];
    const int*   ecol = (const int*)  d_in[2];
    const float* eval = (const float*)d_in[3];
    const float* W    = (const float*)d_in[4];
    const float* bias = (const float*)d_in[5];
    float* out = (float*)d_out;

    const int E  = in_sizes[1];
    const int nb = (M_NODES + SCAN_BS - 1) / SCAN_BS;

    const int GEMM_SMEM = (2 * 128 * 36 + 2 * 32 * 136) * 4;   // 71680 B
    cudaFuncSetAttribute(gemm_tf32_kernel,
                         cudaFuncAttributeMaxDynamicSharedMemorySize, GEMM_SMEM);

    const bool fork = (g_s2 && g_fork && g_join);
    cudaStream_t s2 = fork ? g_s2 : (cudaStream_t)0;

    if (fork) {
        cudaEventRecord(g_fork, 0);
        cudaStreamWaitEvent(s2, g_fork, 0);
    }

    // ---- branch A (side stream): CSR build ----
    hist_kernel<<<(E + 255) / 256, 256, 0, s2>>>(erow, E);
    scan_blocks_kernel<<<nb, SCAN_BS, 0, s2>>>(M_NODES);
    scan_small_kernel<<<1, 128, 0, s2>>>(nb);
    scan_add_kernel<<<(M_NODES + 255) / 256, 256, 0, s2>>>(M_NODES, E);
    permute_kernel<<<(E + 255) / 256, 256, 0, s2>>>(erow, ecol, eval, E);

    if (fork) cudaEventRecord(g_join, s2);

    // ---- branch B (main stream): GEMM ----
    wconv_kernel<<<(K_IN * N_OUT + 255) / 256, 256>>>(W);
    gemm_tf32_kernel<<<(M_NODES + 127) / 128, 256, GEMM_SMEM>>>(x, bias);

    // ---- join, then gather ----
    if (fork) cudaStreamWaitEvent(0, g_join, 0);
    gather_kernel<<<(M_NODES * 32 + 255) / 256, 256>>>(out);
}

// round 8
// speedup vs baseline: 3.2140x; 1.0817x over previous
#include <cuda_runtime.h>
#include <cuda_fp16.h>
#include <cstdint>

#define M_NODES 100000
#define K_IN    256
#define N_OUT   128
#define MAX_E   1600000
#define SCAN_BS 1024

// ---- static device scratch (no allocs allowed) ----
__device__ __half    g_support_h[(size_t)M_NODES * N_OUT];  // 25.6 MB fp16
__device__ uint32_t  g_Wh[(K_IN / 2) * N_OUT];              // W packed half2 (k-pairs)
__device__ int       g_cnt[M_NODES];
__device__ int       g_start[M_NODES + 1];
__device__ int       g_cursor[M_NODES];
__device__ int       g_bsums[128];
__device__ uint2     g_edges[MAX_E];                        // packed (col, val_bits)

__device__ __forceinline__ uint32_t pack_h2(float lo, float hi)
{
    uint32_t r;
    asm("cvt.rn.f16x2.f32 %0, %1, %2;" : "=r"(r) : "f"(hi), "f"(lo));
    return r;
}

__device__ __forceinline__ void cp_async16(uint32_t saddr, const void* gptr, int srcBytes)
{
    asm volatile("cp.async.cg.shared.global [%0], [%1], 16, %2;\n"
                 :: "r"(saddr), "l"(gptr), "r"(srcBytes));
}
#define CP_COMMIT() asm volatile("cp.async.commit_group;\n" ::)
#define CP_WAIT0()  asm volatile("cp.async.wait_group 0;\n" ::)

// ---------------------------------------------------------------------------
// Kernel 0: W -> packed half2, layout [k/2][n] (matches mma B fragment)
// ---------------------------------------------------------------------------
__global__ void wconv_kernel(const float* __restrict__ W)
{
    int i = blockIdx.x * blockDim.x + threadIdx.x;
    if (i < (K_IN / 2) * N_OUT) {
        int kp = i / N_OUT, n = i % N_OUT;
        g_Wh[i] = pack_h2(W[(2 * kp) * N_OUT + n], W[(2 * kp + 1) * N_OUT + n]);
    }
}

// ---------------------------------------------------------------------------
// Kernel 1: support = x @ W + b  via FP16 mma.sync.m16n8k16, fp32 accumulate.
// cp.async double-buffered. A staged fp32 (stride 40 -> conflict-free float2
// fragment loads), converted to fp16 at fragment load. B staged pre-packed.
// ---------------------------------------------------------------------------
__global__ __launch_bounds__(256) void gemm_fp16_kernel(
    const float* __restrict__ x,
    const float* __restrict__ bias)
{
    extern __shared__ float smf[];
    float*    Asf = smf;                              // [2][128][40] fp32
    uint32_t* Bsf = (uint32_t*)(smf + 2 * 128 * 40);  // [2][16][136] half2

    const int tid   = threadIdx.x;
    const int lane  = tid & 31;
    const int wid   = tid >> 5;
    const int warpM = wid & 3;
    const int warpN = wid >> 2;
    const int g     = lane >> 2;
    const int tg    = lane & 3;
    const int rowBase = blockIdx.x * 128;

    float acc[2][8][4];
    #pragma unroll
    for (int mt = 0; mt < 2; mt++)
        #pragma unroll
        for (int nt = 0; nt < 8; nt++)
            #pragma unroll
            for (int r = 0; r < 4; r++) acc[mt][nt][r] = 0.f;

    const uint32_t aBase[2] = {
        (uint32_t)__cvta_generic_to_shared(Asf),
        (uint32_t)__cvta_generic_to_shared(Asf + 128 * 40) };
    const uint32_t bBase[2] = {
        (uint32_t)__cvta_generic_to_shared(Bsf),
        (uint32_t)__cvta_generic_to_shared(Bsf + 16 * 136) };

    auto loadStage = [&](int kb, int s) {
        // A tile: 128 rows x 32 k fp32 = 1024 x 16B, 4 per thread
        #pragma unroll
        for (int i = 0; i < 4; i++) {
            int idx  = tid + i * 256;
            int row  = idx >> 3;
            int k4   = (idx & 7) * 4;
            int grow = rowBase + row;
            int sz   = (grow < M_NODES) ? 16 : 0;
            const float* src = x + (size_t)min(grow, M_NODES - 1) * K_IN + kb + k4;
            cp_async16(aBase[s] + (uint32_t)(row * 40 + k4) * 4, src, sz);
        }
        // B tile: 16 kpair-rows x 128 n half2 = 512 x 16B, 2 per thread
        #pragma unroll
        for (int i = 0; i < 2; i++) {
            int idx = tid + i * 256;
            int kp  = idx >> 5;
            int n4  = (idx & 31) * 4;
            cp_async16(bBase[s] + (uint32_t)(kp * 136 + n4) * 4,
                       g_Wh + (kb / 2 + kp) * N_OUT + n4, 16);
        }
        CP_COMMIT();
    };

    auto compute = [&](int s) {
        const float*    A = Asf + s * 128 * 40;
        const uint32_t* B = Bsf + s * 16 * 136;
        #pragma unroll
        for (int ks = 0; ks < 2; ks++) {
            const int kk = ks * 16;     // k offset within 32-k tile
            const int kp = ks * 8;      // k-pair row offset in Bs
            uint32_t bfr[8][2];
            #pragma unroll
            for (int nt = 0; nt < 8; nt++) {
                int col = warpN * 64 + nt * 8 + g;
                bfr[nt][0] = B[(kp + tg) * 136 + col];
                bfr[nt][1] = B[(kp + 4 + tg) * 136 + col];
            }
            #pragma unroll
            for (int mt = 0; mt < 2; mt++) {
                int r0 = warpM * 32 + mt * 16 + g;
                const float* Ar0 = A + r0 * 40 + kk;
                const float* Ar1 = A + (r0 + 8) * 40 + kk;
                float2 f0 = *(const float2*)(Ar0 + 2 * tg);
                float2 f1 = *(const float2*)(Ar1 + 2 * tg);
                float2 f2 = *(const float2*)(Ar0 + 2 * tg + 8);
                float2 f3 = *(const float2*)(Ar1 + 2 * tg + 8);
                uint32_t a0 = pack_h2(f0.x, f0.y);
                uint32_t a1 = pack_h2(f1.x, f1.y);
                uint32_t a2 = pack_h2(f2.x, f2.y);
                uint32_t a3 = pack_h2(f3.x, f3.y);
                #pragma unroll
                for (int nt = 0; nt < 8; nt++) {
                    asm volatile(
                        "mma.sync.aligned.m16n8k16.row.col.f32.f16.f16.f32 "
                        "{%0,%1,%2,%3}, {%4,%5,%6,%7}, {%8,%9}, {%0,%1,%2,%3};"
                        : "+f"(acc[mt][nt][0]), "+f"(acc[mt][nt][1]),
                          "+f"(acc[mt][nt][2]), "+f"(acc[mt][nt][3])
                        : "r"(a0), "r"(a1), "r"(a2), "r"(a3),
                          "r"(bfr[nt][0]), "r"(bfr[nt][1]));
                }
            }
        }
    };

    loadStage(0, 0);
    CP_WAIT0();
    __syncthreads();

    #pragma unroll
    for (int kb = 0; kb < 8; kb++) {
        if (kb < 7) loadStage((kb + 1) * 32, (kb + 1) & 1);
        compute(kb & 1);
        if (kb < 7) {
            CP_WAIT0();
            __syncthreads();
        }
    }

    // ---- epilogue: += bias, pack fp16, store ----
    #pragma unroll
    for (int nt = 0; nt < 8; nt++) {
        int col = warpN * 64 + nt * 8 + tg * 2;
        float2 bv = *(const float2*)(bias + col);
        #pragma unroll
        for (int mt = 0; mt < 2; mt++) {
            int row0 = rowBase + warpM * 32 + mt * 16 + g;
            if (row0 < M_NODES) {
                __half2 h = __floats2half2_rn(acc[mt][nt][0] + bv.x,
                                              acc[mt][nt][1] + bv.y);
                *(__half2*)(g_support_h + (size_t)row0 * N_OUT + col) = h;
            }
            int row1 = row0 + 8;
            if (row1 < M_NODES) {
                __half2 h = __floats2half2_rn(acc[mt][nt][2] + bv.x,
                                              acc[mt][nt][3] + bv.y);
                *(__half2*)(g_support_h + (size_t)row1 * N_OUT + col) = h;
            }
        }
    }
}

// ---------------------------------------------------------------------------
// CSR build: histogram -> reduce -> scan+apply -> permute
// ---------------------------------------------------------------------------
__global__ void hist_kernel(const int* __restrict__ erow, int E)
{
    int i = blockIdx.x * blockDim.x + threadIdx.x;
    if (i < E) atomicAdd(&g_cnt[erow[i]], 1);
}

__device__ __forceinline__ int warp_incl_scan(int v, int lane)
{
    #pragma unroll
    for (int off = 1; off < 32; off <<= 1) {
        int t = __shfl_up_sync(0xffffffffu, v, off);
        if (lane >= off) v += t;
    }
    return v;
}

// K1: per-block reduce of g_cnt -> g_bsums
__global__ __launch_bounds__(SCAN_BS) void reduce_kernel(int n)
{
    __shared__ int wsum[32];
    int i    = blockIdx.x * SCAN_BS + threadIdx.x;
    int lane = threadIdx.x & 31;
    int w    = threadIdx.x >> 5;
    int v    = (i < n) ? g_cnt[i] : 0;
    #pragma unroll
    for (int off = 16; off; off >>= 1) v += __shfl_down_sync(0xffffffffu, v, off);
    if (lane == 0) wsum[w] = v;
    __syncthreads();
    if (w == 0) {
        int s = wsum[lane];
        #pragma unroll
        for (int off = 16; off; off >>= 1) s += __shfl_down_sync(0xffffffffu, s, off);
        if (lane == 0) g_bsums[blockIdx.x] = s;
    }
}

// K2: every block scans the (<=128) block sums itself, then block-scans its
// own g_cnt segment, writes g_start/g_cursor, self-cleans g_cnt.
__global__ __launch_bounds__(SCAN_BS) void scan_apply_kernel(int n, int nb, int E)
{
    __shared__ int s_boff;
    __shared__ int wsum[32];
    int i    = blockIdx.x * SCAN_BS + threadIdx.x;
    int lane = threadIdx.x & 31;
    int w    = threadIdx.x >> 5;

    // warp 0: exclusive-scan the block sums, stash this block's offset
    if (w == 0) {
        int run = 0;
        for (int base = 0; base < nb; base += 32) {
            int v    = (base + lane < nb) ? g_bsums[base + lane] : 0;
            int incl = warp_incl_scan(v, lane);
            int excl = run + incl - v;
            if (base + lane == blockIdx.x) s_boff = excl;
            run += __shfl_sync(0xffffffffu, incl, 31);
        }
    }

    int v = (i < n) ? g_cnt[i] : 0;
    if (i < n) g_cnt[i] = 0;                     // self-clean for next replay

    int incl = warp_incl_scan(v, lane);
    if (lane == 31) wsum[w] = incl;
    __syncthreads();
    if (w == 0) {
        int s  = wsum[lane];
        int ws = warp_incl_scan(s, lane);
        wsum[lane] = ws - s;
    }
    __syncthreads();

    if (i < n) {
        int s = s_boff + wsum[w] + incl - v;
        g_start[i]  = s;
        g_cursor[i] = s;
    }
    if (blockIdx.x == 0 && threadIdx.x == 0) g_start[n] = E;
}

__global__ void permute_kernel(const int* __restrict__ erow,
                               const int* __restrict__ ecol,
                               const float* __restrict__ eval, int E)
{
    int i = blockIdx.x * blockDim.x + threadIdx.x;
    if (i < E) {
        int r   = erow[i];
        int pos = atomicAdd(&g_cursor[r], 1);
        g_edges[pos] = make_uint2((unsigned)ecol[i], __float_as_uint(eval[i]));
    }
}

// ---------------------------------------------------------------------------
// Gather: one warp per row, lane owns 4 features; uniform edge loads
// (HW broadcast), 4 independent support gathers in flight.
// ---------------------------------------------------------------------------
__global__ __launch_bounds__(256) void gather_kernel(float* __restrict__ out)
{
    int row  = (blockIdx.x * blockDim.x + threadIdx.x) >> 5;
    int lane = threadIdx.x & 31;
    if (row >= M_NODES) return;

    int s = g_start[row];
    int e = g_start[row + 1];

    const uint2* sup = (const uint2*)g_support_h;

    float4 acc0 = make_float4(0.f, 0.f, 0.f, 0.f);
    float4 acc1 = make_float4(0.f, 0.f, 0.f, 0.f);

    int j = s;
    for (; j + 4 <= e; j += 4) {
        uint2 e0 = __ldg(&g_edges[j + 0]);
        uint2 e1 = __ldg(&g_edges[j + 1]);
        uint2 e2 = __ldg(&g_edges[j + 2]);
        uint2 e3 = __ldg(&g_edges[j + 3]);
        uint2 d0 = __ldg(&sup[(size_t)e0.x * 32 + lane]);
        uint2 d1 = __ldg(&sup[(size_t)e1.x * 32 + lane]);
        uint2 d2 = __ldg(&sup[(size_t)e2.x * 32 + lane]);
        uint2 d3 = __ldg(&sup[(size_t)e3.x * 32 + lane]);

        float v0 = __uint_as_float(e0.y);
        float v1 = __uint_as_float(e1.y);
        float v2 = __uint_as_float(e2.y);
        float v3 = __uint_as_float(e3.y);

        float2 a, b;
        a = __half22float2(*(__half2*)&d0.x); b = __half22float2(*(__half2*)&d0.y);
        acc0.x += v0 * a.x; acc0.y += v0 * a.y; acc0.z += v0 * b.x; acc0.w += v0 * b.y;
        a = __half22float2(*(__half2*)&d1.x); b = __half22float2(*(__half2*)&d1.y);
        acc1.x += v1 * a.x; acc1.y += v1 * a.y; acc1.z += v1 * b.x; acc1.w += v1 * b.y;
        a = __half22float2(*(__half2*)&d2.x); b = __half22float2(*(__half2*)&d2.y);
        acc0.x += v2 * a.x; acc0.y += v2 * a.y; acc0.z += v2 * b.x; acc0.w += v2 * b.y;
        a = __half22float2(*(__half2*)&d3.x); b = __half22float2(*(__half2*)&d3.y);
        acc1.x += v3 * a.x; acc1.y += v3 * a.y; acc1.z += v3 * b.x; acc1.w += v3 * b.y;
    }
    for (; j < e; j++) {
        uint2 e0 = __ldg(&g_edges[j]);
        uint2 d0 = __ldg(&sup[(size_t)e0.x * 32 + lane]);
        float v0 = __uint_as_float(e0.y);
        float2 a = __half22float2(*(__half2*)&d0.x);
        float2 b = __half22float2(*(__half2*)&d0.y);
        acc0.x += v0 * a.x; acc0.y += v0 * a.y; acc0.z += v0 * b.x; acc0.w += v0 * b.y;
    }

    float4 o;
    o.x = fmaxf(acc0.x + acc1.x, 0.f);
    o.y = fmaxf(acc0.y + acc1.y, 0.f);
    o.z = fmaxf(acc0.z + acc1.z, 0.f);
    o.w = fmaxf(acc0.w + acc1.w, 0.f);
    __stcs((float4*)(out + (size_t)row * N_OUT) + lane, o);
}

// ---------------------------------------------------------------------------
// Side stream + fork/join events, created once at load time.
// ---------------------------------------------------------------------------
static cudaStream_t g_s2   = nullptr;
static cudaEvent_t  g_fork = nullptr;
static cudaEvent_t  g_join = nullptr;
namespace {
struct StreamInit {
    StreamInit() {
        if (cudaStreamCreateWithFlags(&g_s2, cudaStreamNonBlocking) != cudaSuccess) g_s2 = nullptr;
        if (cudaEventCreateWithFlags(&g_fork, cudaEventDisableTiming) != cudaSuccess) g_fork = nullptr;
        if (cudaEventCreateWithFlags(&g_join, cudaEventDisableTiming) != cudaSuccess) g_join = nullptr;
    }
};
static StreamInit g_streamInit;
}

// ---------------------------------------------------------------------------
extern "C" void kernel_launch(void* const* d_in, const int* in_sizes, int n_in,
                              void* d_out, int out_size)
{
    const float* x    = (const float*)d_in[0];
    const int*   erow = (const int*)  d_in[1];
    const int*   ecol = (const int*)  d_in[2];
    const float* eval = (const float*)d_in[3];
    const float* W    = (const float*)d_in[4];
    const float* bias = (const float*)d_in[5];
    float* out = (float*)d_out;

    const int E  = in_sizes[1];
    const int nb = (M_NODES + SCAN_BS - 1) / SCAN_BS;   // 98

    const int GEMM_SMEM = (2 * 128 * 40 + 2 * 16 * 136) * 4;   // 58368 B
    cudaFuncSetAttribute(gemm_fp16_kernel,
                         cudaFuncAttributeMaxDynamicSharedMemorySize, GEMM_SMEM);

    const bool fork = (g_s2 && g_fork && g_join);
    cudaStream_t s2 = fork ? g_s2 : (cudaStream_t)0;

    if (fork) {
        cudaEventRecord(g_fork, 0);
        cudaStreamWaitEvent(s2, g_fork, 0);
    }

    // ---- branch A (side stream): CSR build ----
    hist_kernel<<<(E + 255) / 256, 256, 0, s2>>>(erow, E);
    reduce_kernel<<<nb, SCAN_BS, 0, s2>>>(M_NODES);
    scan_apply_kernel<<<nb, SCAN_BS, 0, s2>>>(M_NODES, nb, E);
    permute_kernel<<<(E + 255) / 256, 256, 0, s2>>>(erow, ecol, eval, E);

    if (fork) cudaEventRecord(g_join, s2);

    // ---- branch B (main stream): GEMM ----
    wconv_kernel<<<((K_IN / 2) * N_OUT + 255) / 256, 256>>>(W);
    gemm_fp16_kernel<<<(M_NODES + 127) / 128, 256, GEMM_SMEM>>>(x, bias);

    // ---- join, then gather ----
    if (fork) cudaStreamWaitEvent(0, g_join, 0);
    gather_kernel<<<(M_NODES * 32 + 255) / 256, 256>>>(out);
}

// round 9
// speedup vs baseline: 3.3537x; 1.0435x over previous
#include <cuda_runtime.h>
#include <cuda_fp16.h>
#include <cstdint>

#define M_NODES 100000
#define K_IN    256
#define N_OUT   128
#define MAX_E   1600000
#define SCAN_BS 1024

// ---- static device scratch (no allocs allowed) ----
__device__ __half    g_support_h[(size_t)M_NODES * N_OUT];  // 25.6 MB fp16
__device__ uint32_t  g_Wh[(K_IN / 2) * N_OUT];              // W packed half2 (k-pairs)
__device__ int       g_cnt[M_NODES];
__device__ int       g_start[M_NODES + 1];
__device__ int       g_rank[MAX_E];                         // per-edge rank within row
__device__ int       g_bsums[128];
__device__ uint2     g_edges[MAX_E];                        // packed (col, val_bits)

__device__ __forceinline__ uint32_t pack_h2(float lo, float hi)
{
    uint32_t r;
    asm("cvt.rn.f16x2.f32 %0, %1, %2;" : "=r"(r) : "f"(hi), "f"(lo));
    return r;
}

__device__ __forceinline__ void cp_async16(uint32_t saddr, const void* gptr, int srcBytes)
{
    asm volatile("cp.async.cg.shared.global [%0], [%1], 16, %2;\n"
                 :: "r"(saddr), "l"(gptr), "r"(srcBytes));
}
#define CP_COMMIT() asm volatile("cp.async.commit_group;\n" ::)
#define CP_WAIT0()  asm volatile("cp.async.wait_group 0;\n" ::)

// ---------------------------------------------------------------------------
// Kernel 0: W -> packed half2, layout [k/2][n]
// ---------------------------------------------------------------------------
__global__ void wconv_kernel(const float* __restrict__ W)
{
    int i = blockIdx.x * blockDim.x + threadIdx.x;
    if (i < (K_IN / 2) * N_OUT) {
        int kp = i / N_OUT, n = i % N_OUT;
        g_Wh[i] = pack_h2(W[(2 * kp) * N_OUT + n], W[(2 * kp + 1) * N_OUT + n]);
    }
}

// ---------------------------------------------------------------------------
// Kernel 1: support = x @ W + b  via FP16 mma.sync.m16n8k16 (unchanged)
// ---------------------------------------------------------------------------
__global__ __launch_bounds__(256) void gemm_fp16_kernel(
    const float* __restrict__ x,
    const float* __restrict__ bias)
{
    extern __shared__ float smf[];
    float*    Asf = smf;                              // [2][128][40] fp32
    uint32_t* Bsf = (uint32_t*)(smf + 2 * 128 * 40);  // [2][16][136] half2

    const int tid   = threadIdx.x;
    const int lane  = tid & 31;
    const int wid   = tid >> 5;
    const int warpM = wid & 3;
    const int warpN = wid >> 2;
    const int g     = lane >> 2;
    const int tg    = lane & 3;
    const int rowBase = blockIdx.x * 128;

    float acc[2][8][4];
    #pragma unroll
    for (int mt = 0; mt < 2; mt++)
        #pragma unroll
        for (int nt = 0; nt < 8; nt++)
            #pragma unroll
            for (int r = 0; r < 4; r++) acc[mt][nt][r] = 0.f;

    const uint32_t aBase[2] = {
        (uint32_t)__cvta_generic_to_shared(Asf),
        (uint32_t)__cvta_generic_to_shared(Asf + 128 * 40) };
    const uint32_t bBase[2] = {
        (uint32_t)__cvta_generic_to_shared(Bsf),
        (uint32_t)__cvta_generic_to_shared(Bsf + 16 * 136) };

    auto loadStage = [&](int kb, int s) {
        #pragma unroll
        for (int i = 0; i < 4; i++) {
            int idx  = tid + i * 256;
            int row  = idx >> 3;
            int k4   = (idx & 7) * 4;
            int grow = rowBase + row;
            int sz   = (grow < M_NODES) ? 16 : 0;
            const float* src = x + (size_t)min(grow, M_NODES - 1) * K_IN + kb + k4;
            cp_async16(aBase[s] + (uint32_t)(row * 40 + k4) * 4, src, sz);
        }
        #pragma unroll
        for (int i = 0; i < 2; i++) {
            int idx = tid + i * 256;
            int kp  = idx >> 5;
            int n4  = (idx & 31) * 4;
            cp_async16(bBase[s] + (uint32_t)(kp * 136 + n4) * 4,
                       g_Wh + (kb / 2 + kp) * N_OUT + n4, 16);
        }
        CP_COMMIT();
    };

    auto compute = [&](int s) {
        const float*    A = Asf + s * 128 * 40;
        const uint32_t* B = Bsf + s * 16 * 136;
        #pragma unroll
        for (int ks = 0; ks < 2; ks++) {
            const int kk = ks * 16;
            const int kp = ks * 8;
            uint32_t bfr[8][2];
            #pragma unroll
            for (int nt = 0; nt < 8; nt++) {
                int col = warpN * 64 + nt * 8 + g;
                bfr[nt][0] = B[(kp + tg) * 136 + col];
                bfr[nt][1] = B[(kp + 4 + tg) * 136 + col];
            }
            #pragma unroll
            for (int mt = 0; mt < 2; mt++) {
                int r0 = warpM * 32 + mt * 16 + g;
                const float* Ar0 = A + r0 * 40 + kk;
                const float* Ar1 = A + (r0 + 8) * 40 + kk;
                float2 f0 = *(const float2*)(Ar0 + 2 * tg);
                float2 f1 = *(const float2*)(Ar1 + 2 * tg);
                float2 f2 = *(const float2*)(Ar0 + 2 * tg + 8);
                float2 f3 = *(const float2*)(Ar1 + 2 * tg + 8);
                uint32_t a0 = pack_h2(f0.x, f0.y);
                uint32_t a1 = pack_h2(f1.x, f1.y);
                uint32_t a2 = pack_h2(f2.x, f2.y);
                uint32_t a3 = pack_h2(f3.x, f3.y);
                #pragma unroll
                for (int nt = 0; nt < 8; nt++) {
                    asm volatile(
                        "mma.sync.aligned.m16n8k16.row.col.f32.f16.f16.f32 "
                        "{%0,%1,%2,%3}, {%4,%5,%6,%7}, {%8,%9}, {%0,%1,%2,%3};"
                        : "+f"(acc[mt][nt][0]), "+f"(acc[mt][nt][1]),
                          "+f"(acc[mt][nt][2]), "+f"(acc[mt][nt][3])
                        : "r"(a0), "r"(a1), "r"(a2), "r"(a3),
                          "r"(bfr[nt][0]), "r"(bfr[nt][1]));
                }
            }
        }
    };

    loadStage(0, 0);
    CP_WAIT0();
    __syncthreads();

    #pragma unroll
    for (int kb = 0; kb < 8; kb++) {
        if (kb < 7) loadStage((kb + 1) * 32, (kb + 1) & 1);
        compute(kb & 1);
        if (kb < 7) {
            CP_WAIT0();
            __syncthreads();
        }
    }

    #pragma unroll
    for (int nt = 0; nt < 8; nt++) {
        int col = warpN * 64 + nt * 8 + tg * 2;
        float2 bv = *(const float2*)(bias + col);
        #pragma unroll
        for (int mt = 0; mt < 2; mt++) {
            int row0 = rowBase + warpM * 32 + mt * 16 + g;
            if (row0 < M_NODES) {
                __half2 h = __floats2half2_rn(acc[mt][nt][0] + bv.x,
                                              acc[mt][nt][1] + bv.y);
                *(__half2*)(g_support_h + (size_t)row0 * N_OUT + col) = h;
            }
            int row1 = row0 + 8;
            if (row1 < M_NODES) {
                __half2 h = __floats2half2_rn(acc[mt][nt][2] + bv.x,
                                              acc[mt][nt][3] + bv.y);
                *(__half2*)(g_support_h + (size_t)row1 * N_OUT + col) = h;
            }
        }
    }
}

// ---------------------------------------------------------------------------
// CSR build: hist(+rank) -> reduce -> scan+apply -> permute (atomic-free)
// ---------------------------------------------------------------------------
__global__ void hist_kernel(const int* __restrict__ erow, int E)
{
    int i = blockIdx.x * blockDim.x + threadIdx.x;
    if (i < E) g_rank[i] = atomicAdd(&g_cnt[erow[i]], 1);
}

__device__ __forceinline__ int warp_incl_scan(int v, int lane)
{
    #pragma unroll
    for (int off = 1; off < 32; off <<= 1) {
        int t = __shfl_up_sync(0xffffffffu, v, off);
        if (lane >= off) v += t;
    }
    return v;
}

__global__ __launch_bounds__(SCAN_BS) void reduce_kernel(int n)
{
    __shared__ int wsum[32];
    int i    = blockIdx.x * SCAN_BS + threadIdx.x;
    int lane = threadIdx.x & 31;
    int w    = threadIdx.x >> 5;
    int v    = (i < n) ? g_cnt[i] : 0;
    #pragma unroll
    for (int off = 16; off; off >>= 1) v += __shfl_down_sync(0xffffffffu, v, off);
    if (lane == 0) wsum[w] = v;
    __syncthreads();
    if (w == 0) {
        int s = wsum[lane];
        #pragma unroll
        for (int off = 16; off; off >>= 1) s += __shfl_down_sync(0xffffffffu, s, off);
        if (lane == 0) g_bsums[blockIdx.x] = s;
    }
}

__global__ __launch_bounds__(SCAN_BS) void scan_apply_kernel(int n, int nb, int E)
{
    __shared__ int s_boff;
    __shared__ int wsum[32];
    int i    = blockIdx.x * SCAN_BS + threadIdx.x;
    int lane = threadIdx.x & 31;
    int w    = threadIdx.x >> 5;

    if (w == 0) {
        int run = 0;
        for (int base = 0; base < nb; base += 32) {
            int v    = (base + lane < nb) ? g_bsums[base + lane] : 0;
            int incl = warp_incl_scan(v, lane);
            int excl = run + incl - v;
            if (base + lane == blockIdx.x) s_boff = excl;
            run += __shfl_sync(0xffffffffu, incl, 31);
        }
    }

    int v = (i < n) ? g_cnt[i] : 0;
    if (i < n) g_cnt[i] = 0;                     // self-clean for next replay

    int incl = warp_incl_scan(v, lane);
    if (lane == 31) wsum[w] = incl;
    __syncthreads();
    if (w == 0) {
        int s  = wsum[lane];
        int ws = warp_incl_scan(s, lane);
        wsum[lane] = ws - s;
    }
    __syncthreads();

    if (i < n) g_start[i] = s_boff + wsum[w] + incl - v;
    if (blockIdx.x == 0 && threadIdx.x == 0) g_start[n] = E;
}

// atomic-free: position = start[row] + precomputed rank
__global__ void permute_kernel(const int* __restrict__ erow,
                               const int* __restrict__ ecol,
                               const float* __restrict__ eval, int E)
{
    int i = blockIdx.x * blockDim.x + threadIdx.x;
    if (i < E) {
        int pos = g_start[erow[i]] + g_rank[i];
        g_edges[pos] = make_uint2((unsigned)ecol[i], __float_as_uint(eval[i]));
    }
}

// ---------------------------------------------------------------------------
// Gather: one warp per row, lane owns 4 features; uniform edge loads,
// 8 independent support gathers in flight (two 4-edge batches).
// ---------------------------------------------------------------------------
__global__ __launch_bounds__(256) void gather_kernel(float* __restrict__ out)
{
    int row  = (blockIdx.x * blockDim.x + threadIdx.x) >> 5;
    int lane = threadIdx.x & 31;
    if (row >= M_NODES) return;

    int s = g_start[row];
    int e = g_start[row + 1];

    const uint2* sup = (const uint2*)g_support_h;

    float4 acc0 = make_float4(0.f, 0.f, 0.f, 0.f);
    float4 acc1 = make_float4(0.f, 0.f, 0.f, 0.f);

    int j = s;
    for (; j + 8 <= e; j += 8) {
        uint2 ee[8], dd[8];
        #pragma unroll
        for (int q = 0; q < 8; q++) ee[q] = __ldg(&g_edges[j + q]);
        #pragma unroll
        for (int q = 0; q < 8; q++) dd[q] = __ldg(&sup[(size_t)ee[q].x * 32 + lane]);
        #pragma unroll
        for (int q = 0; q < 8; q++) {
            float v = __uint_as_float(ee[q].y);
            float2 a = __half22float2(*(__half2*)&dd[q].x);
            float2 b = __half22float2(*(__half2*)&dd[q].y);
            if (q & 1) {
                acc1.x += v * a.x; acc1.y += v * a.y;
                acc1.z += v * b.x; acc1.w += v * b.y;
            } else {
                acc0.x += v * a.x; acc0.y += v * a.y;
                acc0.z += v * b.x; acc0.w += v * b.y;
            }
        }
    }
    if (j + 4 <= e) {
        uint2 ee[4], dd[4];
        #pragma unroll
        for (int q = 0; q < 4; q++) ee[q] = __ldg(&g_edges[j + q]);
        #pragma unroll
        for (int q = 0; q < 4; q++) dd[q] = __ldg(&sup[(size_t)ee[q].x * 32 + lane]);
        #pragma unroll
        for (int q = 0; q < 4; q++) {
            float v = __uint_as_float(ee[q].y);
            float2 a = __half22float2(*(__half2*)&dd[q].x);
            float2 b = __half22float2(*(__half2*)&dd[q].y);
            if (q & 1) {
                acc1.x += v * a.x; acc1.y += v * a.y;
                acc1.z += v * b.x; acc1.w += v * b.y;
            } else {
                acc0.x += v * a.x; acc0.y += v * a.y;
                acc0.z += v * b.x; acc0.w += v * b.y;
            }
        }
        j += 4;
    }
    for (; j < e; j++) {
        uint2 e0 = __ldg(&g_edges[j]);
        uint2 d0 = __ldg(&sup[(size_t)e0.x * 32 + lane]);
        float v0 = __uint_as_float(e0.y);
        float2 a = __half22float2(*(__half2*)&d0.x);
        float2 b = __half22float2(*(__half2*)&d0.y);
        acc0.x += v0 * a.x; acc0.y += v0 * a.y; acc0.z += v0 * b.x; acc0.w += v0 * b.y;
    }

    float4 o;
    o.x = fmaxf(acc0.x + acc1.x, 0.f);
    o.y = fmaxf(acc0.y + acc1.y, 0.f);
    o.z = fmaxf(acc0.z + acc1.z, 0.f);
    o.w = fmaxf(acc0.w + acc1.w, 0.f);
    __stcs((float4*)(out + (size_t)row * N_OUT) + lane, o);
}

// ---------------------------------------------------------------------------
// Side stream + fork/join events, created once at load time.
// ---------------------------------------------------------------------------
static cudaStream_t g_s2   = nullptr;
static cudaEvent_t  g_fork = nullptr;
static cudaEvent_t  g_join = nullptr;
namespace {
struct StreamInit {
    StreamInit() {
        if (cudaStreamCreateWithFlags(&g_s2, cudaStreamNonBlocking) != cudaSuccess) g_s2 = nullptr;
        if (cudaEventCreateWithFlags(&g_fork, cudaEventDisableTiming) != cudaSuccess) g_fork = nullptr;
        if (cudaEventCreateWithFlags(&g_join, cudaEventDisableTiming) != cudaSuccess) g_join = nullptr;
    }
};
static StreamInit g_streamInit;
}

// ---------------------------------------------------------------------------
extern "C" void kernel_launch(void* const* d_in, const int* in_sizes, int n_in,
                              void* d_out, int out_size)
{
    const float* x    = (const float*)d_in[0];
    const int*   erow = (const int*)  d_in[1];
    const int*   ecol = (const int*)  d_in[2];
    const float* eval = (const float*)d_in[3];
    const float* W    = (const float*)d_in[4];
    const float* bias = (const float*)d_in[5];
    float* out = (float*)d_out;

    const int E  = in_sizes[1];
    const int nb = (M_NODES + SCAN_BS - 1) / SCAN_BS;   // 98

    const int GEMM_SMEM = (2 * 128 * 40 + 2 * 16 * 136) * 4;   // 58368 B
    cudaFuncSetAttribute(gemm_fp16_kernel,
                         cudaFuncAttributeMaxDynamicSharedMemorySize, GEMM_SMEM);

    const bool fork = (g_s2 && g_fork && g_join);
    cudaStream_t s2 = fork ? g_s2 : (cudaStream_t)0;

    if (fork) {
        cudaEventRecord(g_fork, 0);
        cudaStreamWaitEvent(s2, g_fork, 0);
    }

    // ---- branch A (side stream): CSR build ----
    hist_kernel<<<(E + 255) / 256, 256, 0, s2>>>(erow, E);
    reduce_kernel<<<nb, SCAN_BS, 0, s2>>>(M_NODES);
    scan_apply_kernel<<<nb, SCAN_BS, 0, s2>>>(M_NODES, nb, E);
    permute_kernel<<<(E + 255) / 256, 256, 0, s2>>>(erow, ecol, eval, E);

    if (fork) cudaEventRecord(g_join, s2);

    // ---- branch B (main stream): GEMM ----
    wconv_kernel<<<((K_IN / 2) * N_OUT + 255) / 256, 256>>>(W);
    gemm_fp16_kernel<<<(M_NODES + 127) / 128, 256, GEMM_SMEM>>>(x, bias);

    // ---- join, then gather ----
    if (fork) cudaStreamWaitEvent(0, g_join, 0);
    gather_kernel<<<(M_NODES * 32 + 255) / 256, 256>>>(out);
}